// round 2
// baseline (speedup 1.0000x reference)
#include <cuda_runtime.h>
#include <math.h>
#include <stdint.h>

// Problem dims (fixed by the dataset)
#define BD   4
#define LD   4096
#define DM   1024
#define DH   2048
#define MROWS (BD * LD)   // 16384

// ---------------- scratch (no allocations allowed) ----------------
__device__ float g_x1 [(size_t)MROWS * DM];  // linear1 out
__device__ float g_xc [(size_t)MROWS * DM];  // conv+silu out
__device__ float g_h1 [(size_t)MROWS * DH];  // dl out -> A_bar
__device__ float g_h2 [(size_t)MROWS * DH];  // A_t out -> h (scan out)
__device__ float g_h3 [(size_t)MROWS * DH];  // B_x out
__device__ float g_ssm[(size_t)MROWS * DM];  // ssm_out
__device__ float g_z  [(size_t)MROWS * DM];  // z

__device__ __forceinline__ float siluf(float x) { return x / (1.0f + expf(-x)); }

// ---------------- SGEMM: C[M,N] = A[M,K] @ B[N,K]^T (+bias) (+epilogue) -----
// BM=BN=128, BK=8, 256 threads, 8x8 per-thread microtile.
enum { EP_NONE = 0, EP_ACCUM = 1, EP_MUL_SILU = 2, EP_ADD_AUX = 3 };

template <int EP>
__global__ __launch_bounds__(256) void sgemm_nt(
    const float* __restrict__ A, const float* __restrict__ Bm,
    const float* __restrict__ bias, const float* __restrict__ aux,
    float* __restrict__ C, int M, int N, int K)
{
    __shared__ float As[8][128];
    __shared__ float Bs[8][128];

    const int tid  = threadIdx.x;
    const int lrow = tid >> 1;        // 0..127
    const int lk   = (tid & 1) * 4;   // 0 or 4

    const float* Ap = A  + (size_t)(blockIdx.y * 128 + lrow) * K + lk;
    const float* Bp = Bm + (size_t)(blockIdx.x * 128 + lrow) * K + lk;

    const int tr = tid >> 4;   // 0..15
    const int tc = tid & 15;   // 0..15

    float acc[8][8];
#pragma unroll
    for (int i = 0; i < 8; i++)
#pragma unroll
        for (int j = 0; j < 8; j++) acc[i][j] = 0.0f;

    for (int k0 = 0; k0 < K; k0 += 8) {
        float4 av = *reinterpret_cast<const float4*>(Ap + k0);
        float4 bv = *reinterpret_cast<const float4*>(Bp + k0);
        __syncthreads();
        As[lk + 0][lrow] = av.x; As[lk + 1][lrow] = av.y;
        As[lk + 2][lrow] = av.z; As[lk + 3][lrow] = av.w;
        Bs[lk + 0][lrow] = bv.x; Bs[lk + 1][lrow] = bv.y;
        Bs[lk + 2][lrow] = bv.z; Bs[lk + 3][lrow] = bv.w;
        __syncthreads();
#pragma unroll
        for (int kk = 0; kk < 8; kk++) {
            float4 a0 = *reinterpret_cast<const float4*>(&As[kk][tr * 4]);
            float4 a1 = *reinterpret_cast<const float4*>(&As[kk][64 + tr * 4]);
            float4 b0 = *reinterpret_cast<const float4*>(&Bs[kk][tc * 4]);
            float4 b1 = *reinterpret_cast<const float4*>(&Bs[kk][64 + tc * 4]);
            float a[8] = {a0.x, a0.y, a0.z, a0.w, a1.x, a1.y, a1.z, a1.w};
            float b[8] = {b0.x, b0.y, b0.z, b0.w, b1.x, b1.y, b1.z, b1.w};
#pragma unroll
            for (int i = 0; i < 8; i++)
#pragma unroll
                for (int j = 0; j < 8; j++)
                    acc[i][j] = fmaf(a[i], b[j], acc[i][j]);
        }
    }

    // epilogue: rows = {tr*4+i, 64+tr*4+i}, cols = {tc*4+j, 64+tc*4+j}
#pragma unroll
    for (int ih = 0; ih < 2; ih++) {
#pragma unroll
        for (int i = 0; i < 4; i++) {
            int row = blockIdx.y * 128 + ih * 64 + tr * 4 + i;
#pragma unroll
            for (int jh = 0; jh < 2; jh++) {
                int col0 = blockIdx.x * 128 + jh * 64 + tc * 4;
                size_t idx = (size_t)row * N + col0;
                float4 v;
                float* vv = &v.x;
#pragma unroll
                for (int j = 0; j < 4; j++) {
                    float r = acc[ih * 4 + i][jh * 4 + j];
                    if (bias) r += bias[col0 + j];
                    if (EP == EP_ACCUM)         r = r + C[idx + j];
                    else if (EP == EP_MUL_SILU) r = aux[idx + j] * siluf(r);
                    else if (EP == EP_ADD_AUX)  r = aux[idx + j] + r;
                    vv[j] = r;
                }
                *reinterpret_cast<float4*>(&C[idx]) = v;
            }
        }
    }
}

// -------------- depthwise conv1d (k=3, pad=1) + bias + SiLU -----------------
// x,y layout [B, L, D]; conv over L per channel d. Cross-correlation (torch).
__global__ void conv_silu_kernel(const float* __restrict__ x,
                                 const float* __restrict__ w,   // [D,1,3]
                                 const float* __restrict__ b,   // [D]
                                 float* __restrict__ y)
{
    size_t idx = (size_t)blockIdx.x * blockDim.x + threadIdx.x;
    const size_t n = (size_t)MROWS * DM;
    if (idx >= n) return;
    int d = (int)(idx % DM);
    int l = (int)((idx / DM) % LD);
    float w0 = w[d * 3 + 0], w1 = w[d * 3 + 1], w2 = w[d * 3 + 2];
    float s = b[d] + w1 * x[idx];
    if (l > 0)      s += w0 * x[idx - DM];
    if (l < LD - 1) s += w2 * x[idx + DM];
    y[idx] = siluf(s);
}

// -------------- A_bar = exp(-softplus(dl) * A_t) (in place over dl) ---------
__global__ void abar_kernel(float* __restrict__ dl, const float* __restrict__ At)
{
    size_t idx = (size_t)blockIdx.x * blockDim.x + threadIdx.x;
    const size_t n = (size_t)MROWS * DH;
    if (idx >= n) return;
    float xd = dl[idx];
    float sp = (xd > 20.0f) ? xd : log1pf(expf(xd));
    dl[idx] = expf(-sp * At[idx]);
}

// -------------- linear scan over L: a*=Abar; s+=Bx*a; h=s -------------------
// one thread per (b, h-channel); coalesced across H at each t.
__global__ void scan_kernel(const float* __restrict__ Abar,
                            const float* __restrict__ Bx,
                            float* __restrict__ h)
{
    int ch = blockIdx.x * blockDim.x + threadIdx.x;   // 0 .. B*DH-1
    if (ch >= BD * DH) return;
    int b  = ch / DH;
    int hh = ch % DH;
    size_t base = (size_t)b * LD * DH + hh;
    float a = 1.0f, s = 0.0f;
#pragma unroll 4
    for (int t = 0; t < LD; t++) {
        size_t i = base + (size_t)t * DH;
        a = a * Abar[i];
        s = fmaf(Bx[i], a, s);
        h[i] = s;
    }
}

// ---------------------------------------------------------------------------
extern "C" void kernel_launch(void* const* d_in, const int* in_sizes, int n_in,
                              void* d_out, int out_size)
{
    const float* x      = (const float*)d_in[0];
    const float* w1     = (const float*)d_in[1];
    const float* w2     = (const float*)d_in[2];
    const float* w3     = (const float*)d_in[3];
    const float* conv_w = (const float*)d_in[4];
    const float* conv_b = (const float*)d_in[5];
    const float* A_w    = (const float*)d_in[6];
    const float* A_b    = (const float*)d_in[7];
    const float* B_w    = (const float*)d_in[8];
    const float* B_b    = (const float*)d_in[9];
    const float* C_w    = (const float*)d_in[10];
    const float* C_b    = (const float*)d_in[11];
    const float* D_w    = (const float*)d_in[12];
    const float* D_b    = (const float*)d_in[13];
    const float* dl_w   = (const float*)d_in[14];
    const float* dl_b   = (const float*)d_in[15];
    float* out = (float*)d_out;

    float *x1, *xc, *h1, *h2, *h3, *ssm, *z;
    cudaGetSymbolAddress((void**)&x1,  g_x1);
    cudaGetSymbolAddress((void**)&xc,  g_xc);
    cudaGetSymbolAddress((void**)&h1,  g_h1);
    cudaGetSymbolAddress((void**)&h2,  g_h2);
    cudaGetSymbolAddress((void**)&h3,  g_h3);
    cudaGetSymbolAddress((void**)&ssm, g_ssm);
    cudaGetSymbolAddress((void**)&z,   g_z);

    const dim3 blk(256);
    const dim3 gD(DM / 128, MROWS / 128);  // N=1024
    const dim3 gH(DH / 128, MROWS / 128);  // N=2048

    // 1) x1 = x @ w1^T
    sgemm_nt<EP_NONE><<<gD, blk>>>(x, w1, nullptr, nullptr, x1, MROWS, DM, DM);
    // 2) xc = silu(depthwise_conv(x1) + conv_b)
    {
        size_t n = (size_t)MROWS * DM;
        conv_silu_kernel<<<(unsigned)((n + 255) / 256), 256>>>(x1, conv_w, conv_b, xc);
    }
    // 3) h1 = xc @ dl_w^T + dl_b     (delta pre-activation)
    sgemm_nt<EP_NONE><<<gH, blk>>>(xc, dl_w, dl_b, nullptr, h1, MROWS, DH, DM);
    // 4) h2 = xc @ A_w^T + A_b       (A_t)
    sgemm_nt<EP_NONE><<<gH, blk>>>(xc, A_w, A_b, nullptr, h2, MROWS, DH, DM);
    // 5) h3 = xc @ B_w^T + B_b       (B_x)
    sgemm_nt<EP_NONE><<<gH, blk>>>(xc, B_w, B_b, nullptr, h3, MROWS, DH, DM);
    // 6) h1 = exp(-softplus(h1) * h2)  (A_bar, in place)
    {
        size_t n = (size_t)MROWS * DH;
        abar_kernel<<<(unsigned)((n + 255) / 256), 256>>>(h1, h2);
    }
    // 7) h2 = scan(h1, h3)           (h)
    scan_kernel<<<(BD * DH + 255) / 256, 256>>>(h1, h3, h2);
    // 8) ssm = h2 @ C_w^T + C_b
    sgemm_nt<EP_NONE><<<gD, blk>>>(h2, C_w, C_b, nullptr, ssm, MROWS, DM, DH);
    // 9) ssm += xc @ D_w^T + D_b
    sgemm_nt<EP_ACCUM><<<gD, blk>>>(xc, D_w, D_b, nullptr, ssm, MROWS, DM, DM);
    // 10) z = ssm * silu(ssm @ w2^T)
    sgemm_nt<EP_MUL_SILU><<<gD, blk>>>(ssm, w2, nullptr, ssm, z, MROWS, DM, DM);
    // 11) out = ssm + z @ w3^T
    sgemm_nt<EP_ADD_AUX><<<gD, blk>>>(z, w3, nullptr, ssm, out, MROWS, DM, DM);
}

// round 7
// speedup vs baseline: 2.1463x; 2.1463x over previous
#include <cuda_runtime.h>
#include <cuda_bf16.h>
#include <math.h>
#include <stdint.h>

// Problem dims (fixed by the dataset)
#define BD   4
#define LSEQ 4096
#define DM   1024
#define DH   2048
#define MROWS (BD * LSEQ)   // 16384

static constexpr size_t SZ_D = (size_t)MROWS * DM;   // 16.78M
static constexpr size_t SZ_H = (size_t)MROWS * DH;   // 33.55M

// ---------------- scratch (no allocations allowed) ----------------
__device__ float g_x1 [SZ_D];
__device__ float g_h1 [SZ_H];
__device__ float g_h2 [SZ_H];
__device__ float g_h3 [SZ_H];
__device__ float g_ssm[SZ_D];
__device__ float g_z  [SZ_D];

// bf16 hi/lo planes for activations
__device__ uint16_t gxh [SZ_D], gxl [SZ_D];
__device__ uint16_t gxch[SZ_D], gxcl[SZ_D];
__device__ uint16_t ghh [SZ_H], ghl [SZ_H];
__device__ uint16_t gsh [SZ_D], gsl [SZ_D];
__device__ uint16_t gzh [SZ_D], gzl [SZ_D];
// weights hi/lo
__device__ uint16_t gw1h[DM * DM], gw1l[DM * DM];
__device__ uint16_t gw2h[DM * DM], gw2l[DM * DM];
__device__ uint16_t gw3h[DM * DM], gw3l[DM * DM];
__device__ uint16_t gDwh[DM * DM], gDwl[DM * DM];
__device__ uint16_t gAwh[DH * DM], gAwl[DH * DM];
__device__ uint16_t gBwh[DH * DM], gBwl[DH * DM];
__device__ uint16_t gdlh[DH * DM], gdll[DH * DM];
__device__ uint16_t gCwh[DM * DH], gCwl[DM * DH];

__device__ __forceinline__ float siluf(float x) { return x / (1.0f + expf(-x)); }

__device__ __forceinline__ uint32_t smem_u32(const void* p) {
    uint32_t a;
    asm("{ .reg .u64 t; cvta.to.shared.u64 t, %1; cvt.u32.u64 %0, t; }" : "=r"(a) : "l"(p));
    return a;
}

#define CP_ASYNC16(s, g) \
    asm volatile("cp.async.cg.shared.global [%0], [%1], 16;" :: "r"(s), "l"(g) : "memory")
#define CP_COMMIT() asm volatile("cp.async.commit_group;" ::: "memory")
#define CP_WAIT1()  asm volatile("cp.async.wait_group 1;" ::: "memory")

__device__ __forceinline__ void ldsm4(uint32_t* r, uint32_t addr) {
    asm volatile("ldmatrix.sync.aligned.m8n8.x4.shared.b16 {%0,%1,%2,%3}, [%4];"
                 : "=r"(r[0]), "=r"(r[1]), "=r"(r[2]), "=r"(r[3]) : "r"(addr));
}

__device__ __forceinline__ void mma_bf16(float* c, const uint32_t* a, const uint32_t* b) {
    asm volatile(
        "mma.sync.aligned.m16n8k16.row.col.f32.bf16.bf16.f32 "
        "{%0,%1,%2,%3}, {%4,%5,%6,%7}, {%8,%9}, {%0,%1,%2,%3};"
        : "+f"(c[0]), "+f"(c[1]), "+f"(c[2]), "+f"(c[3])
        : "r"(a[0]), "r"(a[1]), "r"(a[2]), "r"(a[3]), "r"(b[0]), "r"(b[1]));
}

__device__ __forceinline__ uint16_t bf16h(float x) {
    return __bfloat16_as_ushort(__float2bfloat16(x));
}

// ===================== bf16-split GEMM on mma.sync =====================
// C[M,N] = A[M,K] @ B[N,K]^T (+bias) (+epilogue). A,B given as bf16 hi/lo planes.
// CTA 128x128, BK=32 (bf16), 3-stage cp.async pipeline, 8 warps @ 64x32.
enum { EP_NONE = 0, EP_ACCUM = 1, EP_MUL_SILU = 2, EP_ADD_AUX = 3 };

static constexpr int RS    = 80;           // padded SMEM row stride (bytes)
static constexpr int PLANE = 128 * RS;     // 10240
static constexpr int STG   = 4 * PLANE;    // 40960 (Ahi|Alo|Bhi|Blo)
static constexpr int NSTG  = 3;
static constexpr int GEMM_SMEM = NSTG * STG;   // 122880

template <int EP, bool EMIT>
__global__ __launch_bounds__(256) void gemm_mma(
    const uint16_t* __restrict__ Ah, const uint16_t* __restrict__ Al,
    const uint16_t* __restrict__ Bh, const uint16_t* __restrict__ Bl,
    const float* __restrict__ bias, const float* __restrict__ aux,
    float* __restrict__ C, uint16_t* __restrict__ Ch, uint16_t* __restrict__ Cl,
    int M, int N, int K)
{
    extern __shared__ char smem[];
    const uint32_t sb = smem_u32(smem);
    const int tid = threadIdx.x;
    const int wid = tid >> 5, l = tid & 31;
    const int warp_m = (wid >> 2) * 64;
    const int warp_n = (wid & 3) * 32;
    const int mtile = blockIdx.y, ntile = blockIdx.x;
    const int nch = K >> 5;

    // cp.async mapping: per plane each thread moves rows {t/4, t/4+64}, 16B chunk t%4
    const int ld_row = tid >> 2;
    const int ld_ch  = tid & 3;
    const size_t arow = (size_t)mtile * 128;
    const size_t brow = (size_t)ntile * 128;

    auto load_stage = [&](int s, int c) {
        const uint32_t st = sb + s * STG;
        const size_t kc = (size_t)c << 5;
        const uint16_t* gp0 = Ah + (arow + ld_row) * (size_t)K + kc + ld_ch * 8;
        const uint16_t* gp1 = Al + (arow + ld_row) * (size_t)K + kc + ld_ch * 8;
        const uint16_t* gp2 = Bh + (brow + ld_row) * (size_t)K + kc + ld_ch * 8;
        const uint16_t* gp3 = Bl + (brow + ld_row) * (size_t)K + kc + ld_ch * 8;
        const uint32_t s0 = st + ld_row * RS + ld_ch * 16;
        const size_t stp = (size_t)64 * K;
        CP_ASYNC16(s0,                  gp0);
        CP_ASYNC16(s0 + 64 * RS,        gp0 + stp);
        CP_ASYNC16(s0 + PLANE,          gp1);
        CP_ASYNC16(s0 + PLANE + 64*RS,  gp1 + stp);
        CP_ASYNC16(s0 + 2*PLANE,        gp2);
        CP_ASYNC16(s0 + 2*PLANE + 64*RS,gp2 + stp);
        CP_ASYNC16(s0 + 3*PLANE,        gp3);
        CP_ASYNC16(s0 + 3*PLANE + 64*RS,gp3 + stp);
    };

    // ldmatrix lane addresses (within stage 0; add stage offset per use)
    const uint32_t aL = sb + (uint32_t)((warp_m + (l & 7) + ((l >> 3) & 1) * 8) * RS + (l >> 4) * 16);
    const uint32_t bL = sb + 2 * PLANE +
                        (uint32_t)((warp_n + (l & 7) + (l >> 4) * 8) * RS + ((l >> 3) & 1) * 16);

    float acc[4][4][4];
#pragma unroll
    for (int i = 0; i < 4; i++)
#pragma unroll
        for (int j = 0; j < 4; j++)
#pragma unroll
            for (int e = 0; e < 4; e++) acc[i][j][e] = 0.0f;

    load_stage(0, 0); CP_COMMIT();
    load_stage(1, 1); CP_COMMIT();

    for (int c = 0; c < nch; ++c) {
        CP_WAIT1();
        __syncthreads();
        if (c + 2 < nch) load_stage((c + 2) % NSTG, c + 2);
        CP_COMMIT();

        const uint32_t so = (uint32_t)((c % NSTG) * STG);
#pragma unroll
        for (int ks = 0; ks < 2; ++ks) {
            const uint32_t ao = aL + so + ks * 32;
            const uint32_t bo = bL + so + ks * 32;
            uint32_t afh[4][4], afl[4][4], bfh[4][2], bfl[4][2];
#pragma unroll
            for (int mt = 0; mt < 4; ++mt) {
                ldsm4(afh[mt], ao + mt * 16 * RS);
                ldsm4(afl[mt], ao + PLANE + mt * 16 * RS);
            }
#pragma unroll
            for (int j = 0; j < 2; ++j) {
                uint32_t t[4];
                ldsm4(t, bo + j * 16 * RS);
                bfh[2*j][0] = t[0]; bfh[2*j][1] = t[1];
                bfh[2*j+1][0] = t[2]; bfh[2*j+1][1] = t[3];
                ldsm4(t, bo + PLANE + j * 16 * RS);
                bfl[2*j][0] = t[0]; bfl[2*j][1] = t[1];
                bfl[2*j+1][0] = t[2]; bfl[2*j+1][1] = t[3];
            }
#pragma unroll
            for (int mt = 0; mt < 4; ++mt)
#pragma unroll
                for (int nt = 0; nt < 4; ++nt) {
                    mma_bf16(acc[mt][nt], afh[mt], bfh[nt]);
                    mma_bf16(acc[mt][nt], afh[mt], bfl[nt]);
                    mma_bf16(acc[mt][nt], afl[mt], bfh[nt]);
                }
        }
    }

    // epilogue
    const int mrow0 = mtile * 128 + warp_m + (l >> 2);
    const int coln0 = ntile * 128 + warp_n + (l & 3) * 2;
#pragma unroll
    for (int mt = 0; mt < 4; ++mt) {
#pragma unroll
        for (int nt = 0; nt < 4; ++nt) {
            const int col = coln0 + nt * 8;
#pragma unroll
            for (int h = 0; h < 2; ++h) {
                const int row = mrow0 + mt * 16 + h * 8;
                float v0 = acc[mt][nt][h * 2 + 0];
                float v1 = acc[mt][nt][h * 2 + 1];
                if (bias) { v0 += bias[col]; v1 += bias[col + 1]; }
                const size_t idx = (size_t)row * N + col;
                if (EP == EP_ACCUM) {
                    float2 cv = *reinterpret_cast<const float2*>(&C[idx]);
                    v0 += cv.x; v1 += cv.y;
                } else if (EP == EP_MUL_SILU) {
                    float2 av = *reinterpret_cast<const float2*>(&aux[idx]);
                    v0 = av.x * siluf(v0); v1 = av.y * siluf(v1);
                } else if (EP == EP_ADD_AUX) {
                    float2 av = *reinterpret_cast<const float2*>(&aux[idx]);
                    v0 = av.x + v0; v1 = av.y + v1;
                }
                float2 ov; ov.x = v0; ov.y = v1;
                *reinterpret_cast<float2*>(&C[idx]) = ov;
                if (EMIT) {
                    uint16_t h0 = bf16h(v0), h1 = bf16h(v1);
                    float f0 = __bfloat162float(__ushort_as_bfloat16(h0));
                    float f1 = __bfloat162float(__ushort_as_bfloat16(h1));
                    uint16_t l0 = bf16h(v0 - f0), l1 = bf16h(v1 - f1);
                    *reinterpret_cast<uint32_t*>(&Ch[idx]) = ((uint32_t)h1 << 16) | h0;
                    *reinterpret_cast<uint32_t*>(&Cl[idx]) = ((uint32_t)l1 << 16) | l0;
                }
            }
        }
    }
}

// -------------- fp32 -> bf16 hi/lo split (vectorized x4) --------------------
__global__ void cvt_split(const float* __restrict__ x, uint16_t* __restrict__ hi,
                          uint16_t* __restrict__ lo, size_t n4)
{
    size_t i = (size_t)blockIdx.x * blockDim.x + threadIdx.x;
    if (i >= n4) return;
    float4 v = reinterpret_cast<const float4*>(x)[i];
    uint16_t h0 = bf16h(v.x), h1 = bf16h(v.y), h2 = bf16h(v.z), h3 = bf16h(v.w);
    uint16_t l0 = bf16h(v.x - __bfloat162float(__ushort_as_bfloat16(h0)));
    uint16_t l1 = bf16h(v.y - __bfloat162float(__ushort_as_bfloat16(h1)));
    uint16_t l2 = bf16h(v.z - __bfloat162float(__ushort_as_bfloat16(h2)));
    uint16_t l3 = bf16h(v.w - __bfloat162float(__ushort_as_bfloat16(h3)));
    uint2 hp, lp;
    hp.x = ((uint32_t)h1 << 16) | h0; hp.y = ((uint32_t)h3 << 16) | h2;
    lp.x = ((uint32_t)l1 << 16) | l0; lp.y = ((uint32_t)l3 << 16) | l2;
    reinterpret_cast<uint2*>(hi)[i] = hp;
    reinterpret_cast<uint2*>(lo)[i] = lp;
}

// -------------- depthwise conv1d (k=3, pad=1) + bias + SiLU -> bf16 split ---
__global__ void conv_silu_bf16(const float* __restrict__ x,
                               const float* __restrict__ w, const float* __restrict__ b,
                               uint16_t* __restrict__ yh, uint16_t* __restrict__ yl)
{
    size_t idx = (size_t)blockIdx.x * blockDim.x + threadIdx.x;
    const size_t n = (size_t)MROWS * DM;
    if (idx >= n) return;
    int d = (int)(idx % DM);
    int t = (int)((idx / DM) % LSEQ);
    float w0 = w[d * 3 + 0], w1 = w[d * 3 + 1], w2 = w[d * 3 + 2];
    float s = b[d] + w1 * x[idx];
    if (t > 0)        s += w0 * x[idx - DM];
    if (t < LSEQ - 1) s += w2 * x[idx + DM];
    s = siluf(s);
    uint16_t h = bf16h(s);
    yh[idx] = h;
    yl[idx] = bf16h(s - __bfloat162float(__ushort_as_bfloat16(h)));
}

// -------------- A_bar = exp(-softplus(dl) * A_t) (in place over dl) ---------
__global__ void abar_kernel(float* __restrict__ dl, const float* __restrict__ At)
{
    size_t idx = (size_t)blockIdx.x * blockDim.x + threadIdx.x;
    const size_t n = (size_t)MROWS * DH;
    if (idx >= n) return;
    float xd = dl[idx];
    float sp = (xd > 20.0f) ? xd : log1pf(expf(xd));
    dl[idx] = expf(-sp * At[idx]);
}

// -------------- linear scan over L -> h (bf16 split planes) -----------------
__global__ void scan_kernel(const float* __restrict__ Abar,
                            const float* __restrict__ Bx,
                            uint16_t* __restrict__ hh, uint16_t* __restrict__ hl)
{
    int ch = blockIdx.x * blockDim.x + threadIdx.x;   // 0 .. B*DH-1
    if (ch >= BD * DH) return;
    int b  = ch / DH;
    int hc = ch % DH;
    size_t base = (size_t)b * LSEQ * DH + hc;
    float a = 1.0f, s = 0.0f;
#pragma unroll 4
    for (int t = 0; t < LSEQ; t++) {
        size_t i = base + (size_t)t * DH;
        a = a * Abar[i];
        s = fmaf(Bx[i], a, s);
        uint16_t h = bf16h(s);
        hh[i] = h;
        hl[i] = bf16h(s - __bfloat162float(__ushort_as_bfloat16(h)));
    }
}

// ---------------------------------------------------------------------------
static void launch_cvt(const float* src, uint16_t* hi, uint16_t* lo, size_t n) {
    size_t n4 = n / 4;
    cvt_split<<<(unsigned)((n4 + 255) / 256), 256>>>(src, hi, lo, n4);
}

extern "C" void kernel_launch(void* const* d_in, const int* in_sizes, int n_in,
                              void* d_out, int out_size)
{
    const float* x      = (const float*)d_in[0];
    const float* w1     = (const float*)d_in[1];
    const float* w2     = (const float*)d_in[2];
    const float* w3     = (const float*)d_in[3];
    const float* conv_w = (const float*)d_in[4];
    const float* conv_b = (const float*)d_in[5];
    const float* A_w    = (const float*)d_in[6];
    const float* A_b    = (const float*)d_in[7];
    const float* B_w    = (const float*)d_in[8];
    const float* B_b    = (const float*)d_in[9];
    const float* C_w    = (const float*)d_in[10];
    const float* C_b    = (const float*)d_in[11];
    const float* D_w    = (const float*)d_in[12];
    const float* D_b    = (const float*)d_in[13];
    const float* dl_w   = (const float*)d_in[14];
    const float* dl_b   = (const float*)d_in[15];
    float* out = (float*)d_out;

    float *x1, *h1, *h2, *h3, *ssm, *z;
    uint16_t *xh, *xl, *xch, *xcl, *hh, *hl, *sh, *sl, *zh, *zl;
    uint16_t *w1h, *w1l, *w2h, *w2l, *w3h, *w3l, *Dwh, *Dwl;
    uint16_t *Awh, *Awl, *Bwh, *Bwl, *dlh, *dll, *Cwh, *Cwl;
    cudaGetSymbolAddress((void**)&x1,  g_x1);
    cudaGetSymbolAddress((void**)&h1,  g_h1);
    cudaGetSymbolAddress((void**)&h2,  g_h2);
    cudaGetSymbolAddress((void**)&h3,  g_h3);
    cudaGetSymbolAddress((void**)&ssm, g_ssm);
    cudaGetSymbolAddress((void**)&z,   g_z);
    cudaGetSymbolAddress((void**)&xh,  gxh);  cudaGetSymbolAddress((void**)&xl,  gxl);
    cudaGetSymbolAddress((void**)&xch, gxch); cudaGetSymbolAddress((void**)&xcl, gxcl);
    cudaGetSymbolAddress((void**)&hh,  ghh);  cudaGetSymbolAddress((void**)&hl,  ghl);
    cudaGetSymbolAddress((void**)&sh,  gsh);  cudaGetSymbolAddress((void**)&sl,  gsl);
    cudaGetSymbolAddress((void**)&zh,  gzh);  cudaGetSymbolAddress((void**)&zl,  gzl);
    cudaGetSymbolAddress((void**)&w1h, gw1h); cudaGetSymbolAddress((void**)&w1l, gw1l);
    cudaGetSymbolAddress((void**)&w2h, gw2h); cudaGetSymbolAddress((void**)&w2l, gw2l);
    cudaGetSymbolAddress((void**)&w3h, gw3h); cudaGetSymbolAddress((void**)&w3l, gw3l);
    cudaGetSymbolAddress((void**)&Dwh, gDwh); cudaGetSymbolAddress((void**)&Dwl, gDwl);
    cudaGetSymbolAddress((void**)&Awh, gAwh); cudaGetSymbolAddress((void**)&Awl, gAwl);
    cudaGetSymbolAddress((void**)&Bwh, gBwh); cudaGetSymbolAddress((void**)&Bwl, gBwl);
    cudaGetSymbolAddress((void**)&dlh, gdlh); cudaGetSymbolAddress((void**)&dll, gdll);
    cudaGetSymbolAddress((void**)&Cwh, gCwh); cudaGetSymbolAddress((void**)&Cwl, gCwl);

    cudaFuncSetAttribute(gemm_mma<EP_NONE, false>,    cudaFuncAttributeMaxDynamicSharedMemorySize, GEMM_SMEM);
    cudaFuncSetAttribute(gemm_mma<EP_ACCUM, true>,    cudaFuncAttributeMaxDynamicSharedMemorySize, GEMM_SMEM);
    cudaFuncSetAttribute(gemm_mma<EP_MUL_SILU, true>, cudaFuncAttributeMaxDynamicSharedMemorySize, GEMM_SMEM);
    cudaFuncSetAttribute(gemm_mma<EP_ADD_AUX, false>, cudaFuncAttributeMaxDynamicSharedMemorySize, GEMM_SMEM);

    // ---- conversions (weights + input) ----
    launch_cvt(x,    xh,  xl,  SZ_D);
    launch_cvt(w1,   w1h, w1l, (size_t)DM * DM);
    launch_cvt(w2,   w2h, w2l, (size_t)DM * DM);
    launch_cvt(w3,   w3h, w3l, (size_t)DM * DM);
    launch_cvt(D_w,  Dwh, Dwl, (size_t)DM * DM);
    launch_cvt(A_w,  Awh, Awl, (size_t)DH * DM);
    launch_cvt(B_w,  Bwh, Bwl, (size_t)DH * DM);
    launch_cvt(dl_w, dlh, dll, (size_t)DH * DM);
    launch_cvt(C_w,  Cwh, Cwl, (size_t)DM * DH);

    const dim3 blk(256);
    const dim3 gD(DM / 128, MROWS / 128);   // N=1024
    const dim3 gH(DH / 128, MROWS / 128);   // N=2048

    // 1) x1 = x @ w1^T
    gemm_mma<EP_NONE, false><<<gD, blk, GEMM_SMEM>>>(xh, xl, w1h, w1l, nullptr, nullptr,
                                                     x1, nullptr, nullptr, MROWS, DM, DM);
    // 2) xc = silu(conv(x1)+b)  -> bf16 planes
    {
        size_t n = SZ_D;
        conv_silu_bf16<<<(unsigned)((n + 255) / 256), 256>>>(x1, conv_w, conv_b, xch, xcl);
    }
    // 3,4,5) dl / A_t / B_x
    gemm_mma<EP_NONE, false><<<gH, blk, GEMM_SMEM>>>(xch, xcl, dlh, dll, dl_b, nullptr,
                                                     h1, nullptr, nullptr, MROWS, DH, DM);
    gemm_mma<EP_NONE, false><<<gH, blk, GEMM_SMEM>>>(xch, xcl, Awh, Awl, A_b, nullptr,
                                                     h2, nullptr, nullptr, MROWS, DH, DM);
    gemm_mma<EP_NONE, false><<<gH, blk, GEMM_SMEM>>>(xch, xcl, Bwh, Bwl, B_b, nullptr,
                                                     h3, nullptr, nullptr, MROWS, DH, DM);
    // 9) ssm = xc @ D_w^T + D_b   (moved before g8 so g8 can accumulate)
    gemm_mma<EP_NONE, false><<<gD, blk, GEMM_SMEM>>>(xch, xcl, Dwh, Dwl, D_b, nullptr,
                                                     ssm, nullptr, nullptr, MROWS, DM, DM);
    // 6) h1 = exp(-softplus(h1)*h2)
    {
        size_t n = SZ_H;
        abar_kernel<<<(unsigned)((n + 255) / 256), 256>>>(h1, h2);
    }
    // 7) h = scan(h1, h3) -> bf16 planes
    scan_kernel<<<(BD * DH + 255) / 256, 256>>>(h1, h3, hh, hl);
    // 8) ssm += h @ C_w^T + C_b   (emit ssm bf16 planes)
    gemm_mma<EP_ACCUM, true><<<gD, blk, GEMM_SMEM>>>(hh, hl, Cwh, Cwl, C_b, nullptr,
                                                     ssm, sh, sl, MROWS, DM, DH);
    // 10) z = ssm * silu(ssm @ w2^T)  (emit z bf16 planes)
    gemm_mma<EP_MUL_SILU, true><<<gD, blk, GEMM_SMEM>>>(sh, sl, w2h, w2l, nullptr, ssm,
                                                        z, zh, zl, MROWS, DM, DM);
    // 11) out = ssm + z @ w3^T
    gemm_mma<EP_ADD_AUX, false><<<gD, blk, GEMM_SMEM>>>(zh, zl, w3h, w3l, nullptr, ssm,
                                                        out, nullptr, nullptr, MROWS, DM, DM);
}

// round 8
// speedup vs baseline: 2.4571x; 1.1448x over previous
#include <cuda_runtime.h>
#include <cuda_bf16.h>
#include <math.h>
#include <stdint.h>

// Problem dims (fixed by the dataset)
#define BD   4
#define LSEQ 4096
#define DM   1024
#define DH   2048
#define MROWS (BD * LSEQ)   // 16384
#define NCHK 64
#define LCHK 64            // NCHK*LCHK == LSEQ

static constexpr size_t SZ_D = (size_t)MROWS * DM;   // 16.78M
static constexpr size_t SZ_H = (size_t)MROWS * DH;   // 33.55M

// ---------------- scratch (no allocations allowed) ----------------
__device__ float g_x1 [SZ_D];
__device__ float g_h1 [SZ_H];
__device__ float g_h2 [SZ_H];
__device__ float g_h3 [SZ_H];
__device__ float g_ssm[SZ_D];
__device__ float g_z  [SZ_D];
// scan carries: [BD][NCHK][DH]
__device__ float g_P [(size_t)BD * NCHK * DH];
__device__ float g_Q [(size_t)BD * NCHK * DH];

// bf16 hi/lo planes for activations
__device__ uint16_t gxh [SZ_D], gxl [SZ_D];
__device__ uint16_t gxch[SZ_D], gxcl[SZ_D];
__device__ uint16_t ghh [SZ_H], ghl [SZ_H];
__device__ uint16_t gsh [SZ_D], gsl [SZ_D];
__device__ uint16_t gzh [SZ_D], gzl [SZ_D];
// weights hi/lo
__device__ uint16_t gw1h[DM * DM], gw1l[DM * DM];
__device__ uint16_t gw2h[DM * DM], gw2l[DM * DM];
__device__ uint16_t gw3h[DM * DM], gw3l[DM * DM];
__device__ uint16_t gDwh[DM * DM], gDwl[DM * DM];
__device__ uint16_t gAwh[DH * DM], gAwl[DH * DM];
__device__ uint16_t gBwh[DH * DM], gBwl[DH * DM];
__device__ uint16_t gdlh[DH * DM], gdll[DH * DM];
__device__ uint16_t gCwh[DM * DH], gCwl[DM * DH];

__device__ __forceinline__ float siluf(float x) { return x / (1.0f + expf(-x)); }

__device__ __forceinline__ uint32_t smem_u32(const void* p) {
    uint32_t a;
    asm("{ .reg .u64 t; cvta.to.shared.u64 t, %1; cvt.u32.u64 %0, t; }" : "=r"(a) : "l"(p));
    return a;
}

#define CP_ASYNC16(s, g) \
    asm volatile("cp.async.cg.shared.global [%0], [%1], 16;" :: "r"(s), "l"(g) : "memory")
#define CP_COMMIT() asm volatile("cp.async.commit_group;" ::: "memory")
#define CP_WAIT1()  asm volatile("cp.async.wait_group 1;" ::: "memory")

__device__ __forceinline__ void ldsm4(uint32_t* r, uint32_t addr) {
    asm volatile("ldmatrix.sync.aligned.m8n8.x4.shared.b16 {%0,%1,%2,%3}, [%4];"
                 : "=r"(r[0]), "=r"(r[1]), "=r"(r[2]), "=r"(r[3]) : "r"(addr));
}

__device__ __forceinline__ void mma_bf16(float* c, const uint32_t* a, const uint32_t* b) {
    asm volatile(
        "mma.sync.aligned.m16n8k16.row.col.f32.bf16.bf16.f32 "
        "{%0,%1,%2,%3}, {%4,%5,%6,%7}, {%8,%9}, {%0,%1,%2,%3};"
        : "+f"(c[0]), "+f"(c[1]), "+f"(c[2]), "+f"(c[3])
        : "r"(a[0]), "r"(a[1]), "r"(a[2]), "r"(a[3]), "r"(b[0]), "r"(b[1]));
}

__device__ __forceinline__ uint16_t bf16h(float x) {
    return __bfloat16_as_ushort(__float2bfloat16(x));
}

// ===================== bf16-split GEMM on mma.sync =====================
// C[M,N] = A[M,K] @ B[N,K]^T (+bias) (+epilogue). A,B given as bf16 hi/lo planes.
// CTA 128x256, BK=32 (bf16), 3-stage cp.async pipeline, 8 warps @ 64x64.
enum { EP_NONE = 0, EP_ACCUM = 1, EP_MUL_SILU = 2, EP_ADD_AUX = 3 };

static constexpr int RS     = 80;            // padded SMEM row stride (bytes)
static constexpr int APLANE = 128 * RS;      // 10240
static constexpr int BPLANE = 256 * RS;      // 20480
static constexpr int STG    = 2 * APLANE + 2 * BPLANE;   // 61440 (Ahi|Alo|Bhi|Blo)
static constexpr int NSTG   = 3;
static constexpr int GEMM_SMEM = NSTG * STG; // 184320

template <int EP, bool EMIT>
__global__ __launch_bounds__(256, 1) void gemm_mma(
    const uint16_t* __restrict__ Ah, const uint16_t* __restrict__ Al,
    const uint16_t* __restrict__ Bh, const uint16_t* __restrict__ Bl,
    const float* __restrict__ bias, const float* __restrict__ aux,
    float* __restrict__ C, uint16_t* __restrict__ Ch, uint16_t* __restrict__ Cl,
    int M, int N, int K)
{
    extern __shared__ char smem[];
    const uint32_t sb = smem_u32(smem);
    const int tid = threadIdx.x;
    const int wid = tid >> 5, l = tid & 31;
    const int warp_m = (wid >> 2) * 64;
    const int warp_n = (wid & 3) * 64;
    const int mtile = blockIdx.y, ntile = blockIdx.x;
    const int nch = K >> 5;

    // cp.async mapping: ld_row = tid/4 (0..63), chunk = tid%4 (16B each; 64B/row)
    const int ld_row = tid >> 2;
    const int ld_ch  = tid & 3;
    const size_t arow = (size_t)mtile * 128;
    const size_t brow = (size_t)ntile * 256;

    auto load_stage = [&](int s, int c) {
        const uint32_t st = sb + s * STG;
        const size_t kc = (size_t)c << 5;
        const uint16_t* ga0 = Ah + (arow + ld_row) * (size_t)K + kc + ld_ch * 8;
        const uint16_t* ga1 = Al + (arow + ld_row) * (size_t)K + kc + ld_ch * 8;
        const uint16_t* gb0 = Bh + (brow + ld_row) * (size_t)K + kc + ld_ch * 8;
        const uint16_t* gb1 = Bl + (brow + ld_row) * (size_t)K + kc + ld_ch * 8;
        const uint32_t s0 = st + ld_row * RS + ld_ch * 16;
        const size_t stp = (size_t)64 * K;
        // A planes: rows ld_row, ld_row+64
        CP_ASYNC16(s0,                     ga0);
        CP_ASYNC16(s0 + 64 * RS,           ga0 + stp);
        CP_ASYNC16(s0 + APLANE,            ga1);
        CP_ASYNC16(s0 + APLANE + 64 * RS,  ga1 + stp);
        // B planes: rows ld_row + {0,64,128,192}
        const uint32_t b0 = s0 + 2 * APLANE;
#pragma unroll
        for (int rr = 0; rr < 4; ++rr) {
            CP_ASYNC16(b0 + rr * 64 * RS,          gb0 + rr * stp);
            CP_ASYNC16(b0 + BPLANE + rr * 64 * RS, gb1 + rr * stp);
        }
    };

    // ldmatrix lane addresses (within stage 0; add stage offset per use)
    const uint32_t aL = sb + (uint32_t)((warp_m + (l & 7) + ((l >> 3) & 1) * 8) * RS + (l >> 4) * 16);
    const uint32_t bL = sb + 2 * APLANE +
                        (uint32_t)((warp_n + (l & 7) + (l >> 4) * 8) * RS + ((l >> 3) & 1) * 16);

    float acc[4][8][4];
#pragma unroll
    for (int i = 0; i < 4; i++)
#pragma unroll
        for (int j = 0; j < 8; j++)
#pragma unroll
            for (int e = 0; e < 4; e++) acc[i][j][e] = 0.0f;

    load_stage(0, 0); CP_COMMIT();
    load_stage(1, 1); CP_COMMIT();

    for (int c = 0; c < nch; ++c) {
        CP_WAIT1();
        __syncthreads();
        if (c + 2 < nch) load_stage((c + 2) % NSTG, c + 2);
        CP_COMMIT();

        const uint32_t so = (uint32_t)((c % NSTG) * STG);
#pragma unroll
        for (int ks = 0; ks < 2; ++ks) {
            const uint32_t ao = aL + so + ks * 32;
            const uint32_t bo = bL + so + ks * 32;
            uint32_t afh[4][4], afl[4][4];
#pragma unroll
            for (int mt = 0; mt < 4; ++mt) {
                ldsm4(afh[mt], ao + mt * 16 * RS);
                ldsm4(afl[mt], ao + APLANE + mt * 16 * RS);
            }
#pragma unroll
            for (int g = 0; g < 4; ++g) {
                uint32_t th[4], tl[4];
                ldsm4(th, bo + g * 16 * RS);
                ldsm4(tl, bo + BPLANE + g * 16 * RS);
#pragma unroll
                for (int mt = 0; mt < 4; ++mt) {
                    mma_bf16(acc[mt][2*g],   afh[mt], th);
                    mma_bf16(acc[mt][2*g],   afh[mt], tl);
                    mma_bf16(acc[mt][2*g],   afl[mt], th);
                    mma_bf16(acc[mt][2*g+1], afh[mt], th + 2);
                    mma_bf16(acc[mt][2*g+1], afh[mt], tl + 2);
                    mma_bf16(acc[mt][2*g+1], afl[mt], th + 2);
                }
            }
        }
    }

    // epilogue
    const int mrow0 = mtile * 128 + warp_m + (l >> 2);
    const int coln0 = ntile * 256 + warp_n + (l & 3) * 2;
#pragma unroll
    for (int mt = 0; mt < 4; ++mt) {
#pragma unroll
        for (int nt = 0; nt < 8; ++nt) {
            const int col = coln0 + nt * 8;
#pragma unroll
            for (int h = 0; h < 2; ++h) {
                const int row = mrow0 + mt * 16 + h * 8;
                float v0 = acc[mt][nt][h * 2 + 0];
                float v1 = acc[mt][nt][h * 2 + 1];
                if (bias) { v0 += bias[col]; v1 += bias[col + 1]; }
                const size_t idx = (size_t)row * N + col;
                if (EP == EP_ACCUM) {
                    float2 cv = *reinterpret_cast<const float2*>(&C[idx]);
                    v0 += cv.x; v1 += cv.y;
                } else if (EP == EP_MUL_SILU) {
                    float2 av = *reinterpret_cast<const float2*>(&aux[idx]);
                    v0 = av.x * siluf(v0); v1 = av.y * siluf(v1);
                } else if (EP == EP_ADD_AUX) {
                    float2 av = *reinterpret_cast<const float2*>(&aux[idx]);
                    v0 = av.x + v0; v1 = av.y + v1;
                }
                float2 ov; ov.x = v0; ov.y = v1;
                *reinterpret_cast<float2*>(&C[idx]) = ov;
                if (EMIT) {
                    uint16_t h0 = bf16h(v0), h1 = bf16h(v1);
                    float f0 = __bfloat162float(__ushort_as_bfloat16(h0));
                    float f1 = __bfloat162float(__ushort_as_bfloat16(h1));
                    uint16_t l0 = bf16h(v0 - f0), l1 = bf16h(v1 - f1);
                    *reinterpret_cast<uint32_t*>(&Ch[idx]) = ((uint32_t)h1 << 16) | h0;
                    *reinterpret_cast<uint32_t*>(&Cl[idx]) = ((uint32_t)l1 << 16) | l0;
                }
            }
        }
    }
}

// -------------- fp32 -> bf16 hi/lo split (vectorized x4) --------------------
__global__ void cvt_split(const float* __restrict__ x, uint16_t* __restrict__ hi,
                          uint16_t* __restrict__ lo, size_t n4)
{
    size_t i = (size_t)blockIdx.x * blockDim.x + threadIdx.x;
    if (i >= n4) return;
    float4 v = reinterpret_cast<const float4*>(x)[i];
    uint16_t h0 = bf16h(v.x), h1 = bf16h(v.y), h2 = bf16h(v.z), h3 = bf16h(v.w);
    uint16_t l0 = bf16h(v.x - __bfloat162float(__ushort_as_bfloat16(h0)));
    uint16_t l1 = bf16h(v.y - __bfloat162float(__ushort_as_bfloat16(h1)));
    uint16_t l2 = bf16h(v.z - __bfloat162float(__ushort_as_bfloat16(h2)));
    uint16_t l3 = bf16h(v.w - __bfloat162float(__ushort_as_bfloat16(h3)));
    uint2 hp, lp;
    hp.x = ((uint32_t)h1 << 16) | h0; hp.y = ((uint32_t)h3 << 16) | h2;
    lp.x = ((uint32_t)l1 << 16) | l0; lp.y = ((uint32_t)l3 << 16) | l2;
    reinterpret_cast<uint2*>(hi)[i] = hp;
    reinterpret_cast<uint2*>(lo)[i] = lp;
}

// -------------- depthwise conv1d (k=3, pad=1) + bias + SiLU -> bf16 split ---
__global__ void conv_silu_bf16(const float* __restrict__ x,
                               const float* __restrict__ w, const float* __restrict__ b,
                               uint16_t* __restrict__ yh, uint16_t* __restrict__ yl)
{
    size_t idx = (size_t)blockIdx.x * blockDim.x + threadIdx.x;
    const size_t n = (size_t)MROWS * DM;
    if (idx >= n) return;
    int d = (int)(idx % DM);
    int t = (int)((idx / DM) % LSEQ);
    float w0 = w[d * 3 + 0], w1 = w[d * 3 + 1], w2 = w[d * 3 + 2];
    float s = b[d] + w1 * x[idx];
    if (t > 0)        s += w0 * x[idx - DM];
    if (t < LSEQ - 1) s += w2 * x[idx + DM];
    s = siluf(s);
    uint16_t h = bf16h(s);
    yh[idx] = h;
    yl[idx] = bf16h(s - __bfloat162float(__ushort_as_bfloat16(h)));
}

// -------------- A_bar = exp(-softplus(dl) * A_t) (in place over dl) ---------
__global__ void abar_kernel(float* __restrict__ dl, const float* __restrict__ At)
{
    size_t idx = (size_t)blockIdx.x * blockDim.x + threadIdx.x;
    const size_t n = (size_t)MROWS * DH;
    if (idx >= n) return;
    float xd = dl[idx];
    float sp = (xd > 20.0f) ? xd : log1pf(expf(xd));
    dl[idx] = expf(-sp * At[idx]);
}

// -------------- chunked scan: pass 1 (per-chunk aggregates P, Q) ------------
// thread -> (b, chunk, hc). P = prod(A), Q = sum Bx_t * prod_{j<=t} A_j
__global__ void scan_p1(const float* __restrict__ Abar, const float* __restrict__ Bx,
                        float* __restrict__ P, float* __restrict__ Q)
{
    int idx = blockIdx.x * blockDim.x + threadIdx.x;
    const int tot = BD * NCHK * DH;
    if (idx >= tot) return;
    int hc = idx % DH;
    int c  = (idx / DH) % NCHK;
    int b  = idx / (DH * NCHK);
    size_t base = ((size_t)b * LSEQ + (size_t)c * LCHK) * DH + hc;
    float a = 1.0f, q = 0.0f;
#pragma unroll 4
    for (int t = 0; t < LCHK; ++t) {
        size_t i = base + (size_t)t * DH;
        a = a * Abar[i];
        q = fmaf(Bx[i], a, q);
    }
    size_t ci = ((size_t)b * NCHK + c) * DH + hc;
    P[ci] = a; Q[ci] = q;
}

// -------------- pass 2: cross-chunk scan (in-place: P->a_in, Q->s_in) -------
__global__ void scan_p2(float* __restrict__ P, float* __restrict__ Q)
{
    int ch = blockIdx.x * blockDim.x + threadIdx.x;   // 0 .. BD*DH-1
    if (ch >= BD * DH) return;
    int b  = ch / DH;
    int hc = ch % DH;
    float a = 1.0f, s = 0.0f;
    for (int c = 0; c < NCHK; ++c) {
        size_t ci = ((size_t)b * NCHK + c) * DH + hc;
        float tp = P[ci], tq = Q[ci];
        P[ci] = a; Q[ci] = s;
        s = fmaf(a, tq, s);
        a = a * tp;
    }
}

// -------------- pass 3: replay with seeds, emit h (bf16 planes) -------------
__global__ void scan_p3(const float* __restrict__ Abar, const float* __restrict__ Bx,
                        const float* __restrict__ Ain, const float* __restrict__ Sin,
                        uint16_t* __restrict__ hh, uint16_t* __restrict__ hl)
{
    int idx = blockIdx.x * blockDim.x + threadIdx.x;
    const int tot = BD * NCHK * DH;
    if (idx >= tot) return;
    int hc = idx % DH;
    int c  = (idx / DH) % NCHK;
    int b  = idx / (DH * NCHK);
    size_t base = ((size_t)b * LSEQ + (size_t)c * LCHK) * DH + hc;
    size_t ci = ((size_t)b * NCHK + c) * DH + hc;
    float a = Ain[ci], s = Sin[ci];
#pragma unroll 4
    for (int t = 0; t < LCHK; ++t) {
        size_t i = base + (size_t)t * DH;
        a = a * Abar[i];
        s = fmaf(Bx[i], a, s);
        uint16_t h = bf16h(s);
        hh[i] = h;
        hl[i] = bf16h(s - __bfloat162float(__ushort_as_bfloat16(h)));
    }
}

// ---------------------------------------------------------------------------
static void launch_cvt(const float* src, uint16_t* hi, uint16_t* lo, size_t n) {
    size_t n4 = n / 4;
    cvt_split<<<(unsigned)((n4 + 255) / 256), 256>>>(src, hi, lo, n4);
}

extern "C" void kernel_launch(void* const* d_in, const int* in_sizes, int n_in,
                              void* d_out, int out_size)
{
    const float* x      = (const float*)d_in[0];
    const float* w1     = (const float*)d_in[1];
    const float* w2     = (const float*)d_in[2];
    const float* w3     = (const float*)d_in[3];
    const float* conv_w = (const float*)d_in[4];
    const float* conv_b = (const float*)d_in[5];
    const float* A_w    = (const float*)d_in[6];
    const float* A_b    = (const float*)d_in[7];
    const float* B_w    = (const float*)d_in[8];
    const float* B_b    = (const float*)d_in[9];
    const float* C_w    = (const float*)d_in[10];
    const float* C_b    = (const float*)d_in[11];
    const float* D_w    = (const float*)d_in[12];
    const float* D_b    = (const float*)d_in[13];
    const float* dl_w   = (const float*)d_in[14];
    const float* dl_b   = (const float*)d_in[15];
    float* out = (float*)d_out;

    float *x1, *h1, *h2, *h3, *ssm, *z, *Pc, *Qc;
    uint16_t *xh, *xl, *xch, *xcl, *hh, *hl, *sh, *sl, *zh, *zl;
    uint16_t *w1h, *w1l, *w2h, *w2l, *w3h, *w3l, *Dwh, *Dwl;
    uint16_t *Awh, *Awl, *Bwh, *Bwl, *dlh, *dll, *Cwh, *Cwl;
    cudaGetSymbolAddress((void**)&x1,  g_x1);
    cudaGetSymbolAddress((void**)&h1,  g_h1);
    cudaGetSymbolAddress((void**)&h2,  g_h2);
    cudaGetSymbolAddress((void**)&h3,  g_h3);
    cudaGetSymbolAddress((void**)&ssm, g_ssm);
    cudaGetSymbolAddress((void**)&z,   g_z);
    cudaGetSymbolAddress((void**)&Pc,  g_P);
    cudaGetSymbolAddress((void**)&Qc,  g_Q);
    cudaGetSymbolAddress((void**)&xh,  gxh);  cudaGetSymbolAddress((void**)&xl,  gxl);
    cudaGetSymbolAddress((void**)&xch, gxch); cudaGetSymbolAddress((void**)&xcl, gxcl);
    cudaGetSymbolAddress((void**)&hh,  ghh);  cudaGetSymbolAddress((void**)&hl,  ghl);
    cudaGetSymbolAddress((void**)&sh,  gsh);  cudaGetSymbolAddress((void**)&sl,  gsl);
    cudaGetSymbolAddress((void**)&zh,  gzh);  cudaGetSymbolAddress((void**)&zl,  gzl);
    cudaGetSymbolAddress((void**)&w1h, gw1h); cudaGetSymbolAddress((void**)&w1l, gw1l);
    cudaGetSymbolAddress((void**)&w2h, gw2h); cudaGetSymbolAddress((void**)&w2l, gw2l);
    cudaGetSymbolAddress((void**)&w3h, gw3h); cudaGetSymbolAddress((void**)&w3l, gw3l);
    cudaGetSymbolAddress((void**)&Dwh, gDwh); cudaGetSymbolAddress((void**)&Dwl, gDwl);
    cudaGetSymbolAddress((void**)&Awh, gAwh); cudaGetSymbolAddress((void**)&Awl, gAwl);
    cudaGetSymbolAddress((void**)&Bwh, gBwh); cudaGetSymbolAddress((void**)&Bwl, gBwl);
    cudaGetSymbolAddress((void**)&dlh, gdlh); cudaGetSymbolAddress((void**)&dll, gdll);
    cudaGetSymbolAddress((void**)&Cwh, gCwh); cudaGetSymbolAddress((void**)&Cwl, gCwl);

    cudaFuncSetAttribute(gemm_mma<EP_NONE, false>,    cudaFuncAttributeMaxDynamicSharedMemorySize, GEMM_SMEM);
    cudaFuncSetAttribute(gemm_mma<EP_ACCUM, true>,    cudaFuncAttributeMaxDynamicSharedMemorySize, GEMM_SMEM);
    cudaFuncSetAttribute(gemm_mma<EP_MUL_SILU, true>, cudaFuncAttributeMaxDynamicSharedMemorySize, GEMM_SMEM);
    cudaFuncSetAttribute(gemm_mma<EP_ADD_AUX, false>, cudaFuncAttributeMaxDynamicSharedMemorySize, GEMM_SMEM);

    // ---- conversions (weights + input) ----
    launch_cvt(x,    xh,  xl,  SZ_D);
    launch_cvt(w1,   w1h, w1l, (size_t)DM * DM);
    launch_cvt(w2,   w2h, w2l, (size_t)DM * DM);
    launch_cvt(w3,   w3h, w3l, (size_t)DM * DM);
    launch_cvt(D_w,  Dwh, Dwl, (size_t)DM * DM);
    launch_cvt(A_w,  Awh, Awl, (size_t)DH * DM);
    launch_cvt(B_w,  Bwh, Bwl, (size_t)DH * DM);
    launch_cvt(dl_w, dlh, dll, (size_t)DH * DM);
    launch_cvt(C_w,  Cwh, Cwl, (size_t)DM * DH);

    const dim3 blk(256);
    const dim3 gD(DM / 256, MROWS / 128);   // N=1024 -> (4,128)
    const dim3 gH(DH / 256, MROWS / 128);   // N=2048 -> (8,128)

    // 1) x1 = x @ w1^T
    gemm_mma<EP_NONE, false><<<gD, blk, GEMM_SMEM>>>(xh, xl, w1h, w1l, nullptr, nullptr,
                                                     x1, nullptr, nullptr, MROWS, DM, DM);
    // 2) xc = silu(conv(x1)+b)  -> bf16 planes
    {
        size_t n = SZ_D;
        conv_silu_bf16<<<(unsigned)((n + 255) / 256), 256>>>(x1, conv_w, conv_b, xch, xcl);
    }
    // 3,4,5) dl / A_t / B_x
    gemm_mma<EP_NONE, false><<<gH, blk, GEMM_SMEM>>>(xch, xcl, dlh, dll, dl_b, nullptr,
                                                     h1, nullptr, nullptr, MROWS, DH, DM);
    gemm_mma<EP_NONE, false><<<gH, blk, GEMM_SMEM>>>(xch, xcl, Awh, Awl, A_b, nullptr,
                                                     h2, nullptr, nullptr, MROWS, DH, DM);
    gemm_mma<EP_NONE, false><<<gH, blk, GEMM_SMEM>>>(xch, xcl, Bwh, Bwl, B_b, nullptr,
                                                     h3, nullptr, nullptr, MROWS, DH, DM);
    // 9) ssm = xc @ D_w^T + D_b   (moved before g8 so g8 can accumulate)
    gemm_mma<EP_NONE, false><<<gD, blk, GEMM_SMEM>>>(xch, xcl, Dwh, Dwl, D_b, nullptr,
                                                     ssm, nullptr, nullptr, MROWS, DM, DM);
    // 6) h1 = exp(-softplus(h1)*h2)
    {
        size_t n = SZ_H;
        abar_kernel<<<(unsigned)((n + 255) / 256), 256>>>(h1, h2);
    }
    // 7) h = chunked scan(h1, h3) -> bf16 planes
    {
        const int tot = BD * NCHK * DH;
        scan_p1<<<(tot + 255) / 256, 256>>>(h1, h3, Pc, Qc);
        scan_p2<<<(BD * DH + 255) / 256, 256>>>(Pc, Qc);
        scan_p3<<<(tot + 255) / 256, 256>>>(h1, h3, Pc, Qc, hh, hl);
    }
    // 8) ssm += h @ C_w^T + C_b   (emit ssm bf16 planes)
    gemm_mma<EP_ACCUM, true><<<gD, blk, GEMM_SMEM>>>(hh, hl, Cwh, Cwl, C_b, nullptr,
                                                     ssm, sh, sl, MROWS, DM, DH);
    // 10) z = ssm * silu(ssm @ w2^T)  (emit z bf16 planes)
    gemm_mma<EP_MUL_SILU, true><<<gD, blk, GEMM_SMEM>>>(sh, sl, w2h, w2l, nullptr, ssm,
                                                        z, zh, zl, MROWS, DM, DM);
    // 11) out = ssm + z @ w3^T
    gemm_mma<EP_ADD_AUX, false><<<gD, blk, GEMM_SMEM>>>(zh, zl, w3h, w3l, nullptr, ssm,
                                                        out, nullptr, nullptr, MROWS, DM, DM);
}

// round 10
// speedup vs baseline: 2.7539x; 1.1208x over previous
#include <cuda_runtime.h>
#include <cuda_bf16.h>
#include <math.h>
#include <stdint.h>

// Problem dims (fixed by the dataset)
#define BD   4
#define LSEQ 4096
#define DM   1024
#define DH   2048
#define MROWS (BD * LSEQ)   // 16384
#define NCHK 64
#define LCHK 64            // NCHK*LCHK == LSEQ

static constexpr size_t SZ_D = (size_t)MROWS * DM;   // 16.78M
static constexpr size_t SZ_H = (size_t)MROWS * DH;   // 33.55M

// ---------------- scratch (no allocations allowed) ----------------
__device__ float g_x1 [SZ_D];
__device__ float g_h1 [SZ_H];
__device__ float g_h2 [SZ_H];
__device__ float g_h3 [SZ_H];
__device__ float g_ssm[SZ_D];
__device__ float g_z  [SZ_D];
// scan carries: [BD][NCHK][DH]
__device__ float g_P [(size_t)BD * NCHK * DH];
__device__ float g_Q [(size_t)BD * NCHK * DH];

// bf16 hi/lo planes for activations
__device__ uint16_t gxh [SZ_D], gxl [SZ_D];
__device__ uint16_t gxch[SZ_D], gxcl[SZ_D];
__device__ uint16_t ghh [SZ_H], ghl [SZ_H];
__device__ uint16_t gsh [SZ_D], gsl [SZ_D];
__device__ uint16_t gzh [SZ_D], gzl [SZ_D];
// weights hi/lo
__device__ uint16_t gw1h[DM * DM], gw1l[DM * DM];
__device__ uint16_t gw2h[DM * DM], gw2l[DM * DM];
__device__ uint16_t gw3h[DM * DM], gw3l[DM * DM];
__device__ uint16_t gDwh[DM * DM], gDwl[DM * DM];
__device__ uint16_t gAwh[DH * DM], gAwl[DH * DM];
__device__ uint16_t gBwh[DH * DM], gBwl[DH * DM];
__device__ uint16_t gdlh[DH * DM], gdll[DH * DM];
__device__ uint16_t gCwh[DM * DH], gCwl[DM * DH];

__device__ __forceinline__ float siluf(float x) { return x / (1.0f + expf(-x)); }

__device__ __forceinline__ uint32_t smem_u32(const void* p) {
    uint32_t a;
    asm("{ .reg .u64 t; cvta.to.shared.u64 t, %1; cvt.u32.u64 %0, t; }" : "=r"(a) : "l"(p));
    return a;
}

#define CP_ASYNC16(s, g) \
    asm volatile("cp.async.cg.shared.global [%0], [%1], 16;" :: "r"(s), "l"(g) : "memory")
#define CP_COMMIT() asm volatile("cp.async.commit_group;" ::: "memory")
#define CP_WAIT1()  asm volatile("cp.async.wait_group 1;" ::: "memory")
#define CP_WAIT0()  asm volatile("cp.async.wait_group 0;" ::: "memory")

__device__ __forceinline__ void ldsm4(uint32_t* r, uint32_t addr) {
    asm volatile("ldmatrix.sync.aligned.m8n8.x4.shared.b16 {%0,%1,%2,%3}, [%4];"
                 : "=r"(r[0]), "=r"(r[1]), "=r"(r[2]), "=r"(r[3]) : "r"(addr));
}

__device__ __forceinline__ void mma_bf16(float* c, const uint32_t* a, const uint32_t* b) {
    asm volatile(
        "mma.sync.aligned.m16n8k16.row.col.f32.bf16.bf16.f32 "
        "{%0,%1,%2,%3}, {%4,%5,%6,%7}, {%8,%9}, {%0,%1,%2,%3};"
        : "+f"(c[0]), "+f"(c[1]), "+f"(c[2]), "+f"(c[3])
        : "r"(a[0]), "r"(a[1]), "r"(a[2]), "r"(a[3]), "r"(b[0]), "r"(b[1]));
}

__device__ __forceinline__ uint16_t bf16h(float x) {
    return __bfloat16_as_ushort(__float2bfloat16(x));
}

// ===================== bf16-split GEMM on mma.sync =====================
// C[M,N] = A[M,K] @ B[N,K]^T (+bias) (+epilogue). A,B given as bf16 hi/lo planes.
// CTA 128x128, BK=32 (bf16), 2-stage cp.async double buffer, 8 warps @ 64x32,
// 2 CTAs per SM (occupancy overlap hides sync/epilogue bubbles).
enum { EP_NONE = 0, EP_ACCUM = 1, EP_MUL_SILU = 2, EP_ADD_AUX = 3 };

static constexpr int RS    = 80;           // padded SMEM row stride (bytes)
static constexpr int PLANE = 128 * RS;     // 10240
static constexpr int STG   = 4 * PLANE;    // 40960 (Ahi|Alo|Bhi|Blo)
static constexpr int NSTG  = 2;
static constexpr int GEMM_SMEM = NSTG * STG;   // 81920 -> 2 CTAs/SM

template <int EP, bool EMIT>
__global__ __launch_bounds__(256, 2) void gemm_mma(
    const uint16_t* __restrict__ Ah, const uint16_t* __restrict__ Al,
    const uint16_t* __restrict__ Bh, const uint16_t* __restrict__ Bl,
    const float* __restrict__ bias, const float* __restrict__ aux,
    float* __restrict__ C, uint16_t* __restrict__ Ch, uint16_t* __restrict__ Cl,
    int M, int N, int K)
{
    extern __shared__ char smem[];
    const uint32_t sb = smem_u32(smem);
    const int tid = threadIdx.x;
    const int wid = tid >> 5, l = tid & 31;
    const int warp_m = (wid >> 2) * 64;
    const int warp_n = (wid & 3) * 32;
    const int mtile = blockIdx.y, ntile = blockIdx.x;
    const int nch = K >> 5;

    // cp.async mapping: per plane each thread moves rows {t/4, t/4+64}, 16B chunk t%4
    const int ld_row = tid >> 2;
    const int ld_ch  = tid & 3;
    const size_t arow = (size_t)mtile * 128;
    const size_t brow = (size_t)ntile * 128;

    auto load_stage = [&](int s, int c) {
        const uint32_t st = sb + s * STG;
        const size_t kc = (size_t)c << 5;
        const uint16_t* gp0 = Ah + (arow + ld_row) * (size_t)K + kc + ld_ch * 8;
        const uint16_t* gp1 = Al + (arow + ld_row) * (size_t)K + kc + ld_ch * 8;
        const uint16_t* gp2 = Bh + (brow + ld_row) * (size_t)K + kc + ld_ch * 8;
        const uint16_t* gp3 = Bl + (brow + ld_row) * (size_t)K + kc + ld_ch * 8;
        const uint32_t s0 = st + ld_row * RS + ld_ch * 16;
        const size_t stp = (size_t)64 * K;
        CP_ASYNC16(s0,                   gp0);
        CP_ASYNC16(s0 + 64 * RS,         gp0 + stp);
        CP_ASYNC16(s0 + PLANE,           gp1);
        CP_ASYNC16(s0 + PLANE + 64*RS,   gp1 + stp);
        CP_ASYNC16(s0 + 2*PLANE,         gp2);
        CP_ASYNC16(s0 + 2*PLANE + 64*RS, gp2 + stp);
        CP_ASYNC16(s0 + 3*PLANE,         gp3);
        CP_ASYNC16(s0 + 3*PLANE + 64*RS, gp3 + stp);
    };

    // ldmatrix lane addresses (within stage 0; add stage offset per use)
    const uint32_t aL = sb + (uint32_t)((warp_m + (l & 7) + ((l >> 3) & 1) * 8) * RS + (l >> 4) * 16);
    const uint32_t bL = sb + 2 * PLANE +
                        (uint32_t)((warp_n + (l & 7) + (l >> 4) * 8) * RS + ((l >> 3) & 1) * 16);

    float acc[4][4][4];
#pragma unroll
    for (int i = 0; i < 4; i++)
#pragma unroll
        for (int j = 0; j < 4; j++)
#pragma unroll
            for (int e = 0; e < 4; e++) acc[i][j][e] = 0.0f;

    load_stage(0, 0); CP_COMMIT();

    for (int c = 0; c < nch; ++c) {
        __syncthreads();   // prior reads of buffer (c+1)&1 (iter c-1) complete
        if (c + 1 < nch) { load_stage((c + 1) & 1, c + 1); CP_COMMIT(); CP_WAIT1(); }
        else             { CP_WAIT0(); }
        __syncthreads();   // publish stage c arrival to all warps

        const uint32_t so = (uint32_t)((c & 1) * STG);
#pragma unroll
        for (int ks = 0; ks < 2; ++ks) {
            const uint32_t ao = aL + so + ks * 32;
            const uint32_t bo = bL + so + ks * 32;
            uint32_t afh[4][4], afl[4][4], bfh[4][2], bfl[4][2];
#pragma unroll
            for (int mt = 0; mt < 4; ++mt) {
                ldsm4(afh[mt], ao + mt * 16 * RS);
                ldsm4(afl[mt], ao + PLANE + mt * 16 * RS);
            }
#pragma unroll
            for (int j = 0; j < 2; ++j) {
                uint32_t t[4];
                ldsm4(t, bo + j * 16 * RS);
                bfh[2*j][0] = t[0]; bfh[2*j][1] = t[1];
                bfh[2*j+1][0] = t[2]; bfh[2*j+1][1] = t[3];
                ldsm4(t, bo + PLANE + j * 16 * RS);
                bfl[2*j][0] = t[0]; bfl[2*j][1] = t[1];
                bfl[2*j+1][0] = t[2]; bfl[2*j+1][1] = t[3];
            }
#pragma unroll
            for (int mt = 0; mt < 4; ++mt)
#pragma unroll
                for (int nt = 0; nt < 4; ++nt) {
                    mma_bf16(acc[mt][nt], afh[mt], bfh[nt]);
                    mma_bf16(acc[mt][nt], afh[mt], bfl[nt]);
                    mma_bf16(acc[mt][nt], afl[mt], bfh[nt]);
                }
        }
    }

    // epilogue
    const int mrow0 = mtile * 128 + warp_m + (l >> 2);
    const int coln0 = ntile * 128 + warp_n + (l & 3) * 2;
#pragma unroll
    for (int mt = 0; mt < 4; ++mt) {
#pragma unroll
        for (int nt = 0; nt < 4; ++nt) {
            const int col = coln0 + nt * 8;
#pragma unroll
            for (int h = 0; h < 2; ++h) {
                const int row = mrow0 + mt * 16 + h * 8;
                float v0 = acc[mt][nt][h * 2 + 0];
                float v1 = acc[mt][nt][h * 2 + 1];
                if (bias) { v0 += bias[col]; v1 += bias[col + 1]; }
                const size_t idx = (size_t)row * N + col;
                if (EP == EP_ACCUM) {
                    float2 cv = *reinterpret_cast<const float2*>(&C[idx]);
                    v0 += cv.x; v1 += cv.y;
                } else if (EP == EP_MUL_SILU) {
                    float2 av = *reinterpret_cast<const float2*>(&aux[idx]);
                    v0 = av.x * siluf(v0); v1 = av.y * siluf(v1);
                } else if (EP == EP_ADD_AUX) {
                    float2 av = *reinterpret_cast<const float2*>(&aux[idx]);
                    v0 = av.x + v0; v1 = av.y + v1;
                }
                float2 ov; ov.x = v0; ov.y = v1;
                *reinterpret_cast<float2*>(&C[idx]) = ov;
                if (EMIT) {
                    uint16_t h0 = bf16h(v0), h1 = bf16h(v1);
                    float f0 = __bfloat162float(__ushort_as_bfloat16(h0));
                    float f1 = __bfloat162float(__ushort_as_bfloat16(h1));
                    uint16_t l0 = bf16h(v0 - f0), l1 = bf16h(v1 - f1);
                    *reinterpret_cast<uint32_t*>(&Ch[idx]) = ((uint32_t)h1 << 16) | h0;
                    *reinterpret_cast<uint32_t*>(&Cl[idx]) = ((uint32_t)l1 << 16) | l0;
                }
            }
        }
    }
}

// -------------- fp32 -> bf16 hi/lo split (vectorized x4) --------------------
__global__ void cvt_split(const float* __restrict__ x, uint16_t* __restrict__ hi,
                          uint16_t* __restrict__ lo, size_t n4)
{
    size_t i = (size_t)blockIdx.x * blockDim.x + threadIdx.x;
    if (i >= n4) return;
    float4 v = reinterpret_cast<const float4*>(x)[i];
    uint16_t h0 = bf16h(v.x), h1 = bf16h(v.y), h2 = bf16h(v.z), h3 = bf16h(v.w);
    uint16_t l0 = bf16h(v.x - __bfloat162float(__ushort_as_bfloat16(h0)));
    uint16_t l1 = bf16h(v.y - __bfloat162float(__ushort_as_bfloat16(h1)));
    uint16_t l2 = bf16h(v.z - __bfloat162float(__ushort_as_bfloat16(h2)));
    uint16_t l3 = bf16h(v.w - __bfloat162float(__ushort_as_bfloat16(h3)));
    uint2 hp, lp;
    hp.x = ((uint32_t)h1 << 16) | h0; hp.y = ((uint32_t)h3 << 16) | h2;
    lp.x = ((uint32_t)l1 << 16) | l0; lp.y = ((uint32_t)l3 << 16) | l2;
    reinterpret_cast<uint2*>(hi)[i] = hp;
    reinterpret_cast<uint2*>(lo)[i] = lp;
}

// -------------- depthwise conv1d (k=3, pad=1) + bias + SiLU -> bf16 split ---
__global__ void conv_silu_bf16(const float* __restrict__ x,
                               const float* __restrict__ w, const float* __restrict__ b,
                               uint16_t* __restrict__ yh, uint16_t* __restrict__ yl)
{
    size_t idx = (size_t)blockIdx.x * blockDim.x + threadIdx.x;
    const size_t n = (size_t)MROWS * DM;
    if (idx >= n) return;
    int d = (int)(idx % DM);
    int t = (int)((idx / DM) % LSEQ);
    float w0 = w[d * 3 + 0], w1 = w[d * 3 + 1], w2 = w[d * 3 + 2];
    float s = b[d] + w1 * x[idx];
    if (t > 0)        s += w0 * x[idx - DM];
    if (t < LSEQ - 1) s += w2 * x[idx + DM];
    s = siluf(s);
    uint16_t h = bf16h(s);
    yh[idx] = h;
    yl[idx] = bf16h(s - __bfloat162float(__ushort_as_bfloat16(h)));
}

// -------------- A_bar = exp(-softplus(dl) * A_t) (in place over dl) ---------
__global__ void abar_kernel(float* __restrict__ dl, const float* __restrict__ At)
{
    size_t idx = (size_t)blockIdx.x * blockDim.x + threadIdx.x;
    const size_t n = (size_t)MROWS * DH;
    if (idx >= n) return;
    float xd = dl[idx];
    float sp = (xd > 20.0f) ? xd : log1pf(expf(xd));
    dl[idx] = expf(-sp * At[idx]);
}

// -------------- chunked scan: pass 1 (per-chunk aggregates P, Q) ------------
__global__ void scan_p1(const float* __restrict__ Abar, const float* __restrict__ Bx,
                        float* __restrict__ P, float* __restrict__ Q)
{
    int idx = blockIdx.x * blockDim.x + threadIdx.x;
    const int tot = BD * NCHK * DH;
    if (idx >= tot) return;
    int hc = idx % DH;
    int c  = (idx / DH) % NCHK;
    int b  = idx / (DH * NCHK);
    size_t base = ((size_t)b * LSEQ + (size_t)c * LCHK) * DH + hc;
    float a = 1.0f, q = 0.0f;
#pragma unroll 4
    for (int t = 0; t < LCHK; ++t) {
        size_t i = base + (size_t)t * DH;
        a = a * Abar[i];
        q = fmaf(Bx[i], a, q);
    }
    size_t ci = ((size_t)b * NCHK + c) * DH + hc;
    P[ci] = a; Q[ci] = q;
}

// -------------- pass 2: cross-chunk scan (in-place: P->a_in, Q->s_in) -------
__global__ void scan_p2(float* __restrict__ P, float* __restrict__ Q)
{
    int ch = blockIdx.x * blockDim.x + threadIdx.x;   // 0 .. BD*DH-1
    if (ch >= BD * DH) return;
    int b  = ch / DH;
    int hc = ch % DH;
    float a = 1.0f, s = 0.0f;
    for (int c = 0; c < NCHK; ++c) {
        size_t ci = ((size_t)b * NCHK + c) * DH + hc;
        float tp = P[ci], tq = Q[ci];
        P[ci] = a; Q[ci] = s;
        s = fmaf(a, tq, s);
        a = a * tp;
    }
}

// -------------- pass 3: replay with seeds, emit h (bf16 planes) -------------
__global__ void scan_p3(const float* __restrict__ Abar, const float* __restrict__ Bx,
                        const float* __restrict__ Ain, const float* __restrict__ Sin,
                        uint16_t* __restrict__ hh, uint16_t* __restrict__ hl)
{
    int idx = blockIdx.x * blockDim.x + threadIdx.x;
    const int tot = BD * NCHK * DH;
    if (idx >= tot) return;
    int hc = idx % DH;
    int c  = (idx / DH) % NCHK;
    int b  = idx / (DH * NCHK);
    size_t base = ((size_t)b * LSEQ + (size_t)c * LCHK) * DH + hc;
    size_t ci = ((size_t)b * NCHK + c) * DH + hc;
    float a = Ain[ci], s = Sin[ci];
#pragma unroll 4
    for (int t = 0; t < LCHK; ++t) {
        size_t i = base + (size_t)t * DH;
        a = a * Abar[i];
        s = fmaf(Bx[i], a, s);
        uint16_t h = bf16h(s);
        hh[i] = h;
        hl[i] = bf16h(s - __bfloat162float(__ushort_as_bfloat16(h)));
    }
}

// ---------------------------------------------------------------------------
static void launch_cvt(const float* src, uint16_t* hi, uint16_t* lo, size_t n) {
    size_t n4 = n / 4;
    cvt_split<<<(unsigned)((n4 + 255) / 256), 256>>>(src, hi, lo, n4);
}

extern "C" void kernel_launch(void* const* d_in, const int* in_sizes, int n_in,
                              void* d_out, int out_size)
{
    const float* x      = (const float*)d_in[0];
    const float* w1     = (const float*)d_in[1];
    const float* w2     = (const float*)d_in[2];
    const float* w3     = (const float*)d_in[3];
    const float* conv_w = (const float*)d_in[4];
    const float* conv_b = (const float*)d_in[5];
    const float* A_w    = (const float*)d_in[6];
    const float* A_b    = (const float*)d_in[7];
    const float* B_w    = (const float*)d_in[8];
    const float* B_b    = (const float*)d_in[9];
    const float* C_w    = (const float*)d_in[10];
    const float* C_b    = (const float*)d_in[11];
    const float* D_w    = (const float*)d_in[12];
    const float* D_b    = (const float*)d_in[13];
    const float* dl_w   = (const float*)d_in[14];
    const float* dl_b   = (const float*)d_in[15];
    float* out = (float*)d_out;

    float *x1, *h1, *h2, *h3, *ssm, *z, *Pc, *Qc;
    uint16_t *xh, *xl, *xch, *xcl, *hh, *hl, *sh, *sl, *zh, *zl;
    uint16_t *w1h, *w1l, *w2h, *w2l, *w3h, *w3l, *Dwh, *Dwl;
    uint16_t *Awh, *Awl, *Bwh, *Bwl, *dlh, *dll, *Cwh, *Cwl;
    cudaGetSymbolAddress((void**)&x1,  g_x1);
    cudaGetSymbolAddress((void**)&h1,  g_h1);
    cudaGetSymbolAddress((void**)&h2,  g_h2);
    cudaGetSymbolAddress((void**)&h3,  g_h3);
    cudaGetSymbolAddress((void**)&ssm, g_ssm);
    cudaGetSymbolAddress((void**)&z,   g_z);
    cudaGetSymbolAddress((void**)&Pc,  g_P);
    cudaGetSymbolAddress((void**)&Qc,  g_Q);
    cudaGetSymbolAddress((void**)&xh,  gxh);  cudaGetSymbolAddress((void**)&xl,  gxl);
    cudaGetSymbolAddress((void**)&xch, gxch); cudaGetSymbolAddress((void**)&xcl, gxcl);
    cudaGetSymbolAddress((void**)&hh,  ghh);  cudaGetSymbolAddress((void**)&hl,  ghl);
    cudaGetSymbolAddress((void**)&sh,  gsh);  cudaGetSymbolAddress((void**)&sl,  gsl);
    cudaGetSymbolAddress((void**)&zh,  gzh);  cudaGetSymbolAddress((void**)&zl,  gzl);
    cudaGetSymbolAddress((void**)&w1h, gw1h); cudaGetSymbolAddress((void**)&w1l, gw1l);
    cudaGetSymbolAddress((void**)&w2h, gw2h); cudaGetSymbolAddress((void**)&w2l, gw2l);
    cudaGetSymbolAddress((void**)&w3h, gw3h); cudaGetSymbolAddress((void**)&w3l, gw3l);
    cudaGetSymbolAddress((void**)&Dwh, gDwh); cudaGetSymbolAddress((void**)&Dwl, gDwl);
    cudaGetSymbolAddress((void**)&Awh, gAwh); cudaGetSymbolAddress((void**)&Awl, gAwl);
    cudaGetSymbolAddress((void**)&Bwh, gBwh); cudaGetSymbolAddress((void**)&Bwl, gBwl);
    cudaGetSymbolAddress((void**)&dlh, gdlh); cudaGetSymbolAddress((void**)&dll, gdll);
    cudaGetSymbolAddress((void**)&Cwh, gCwh); cudaGetSymbolAddress((void**)&Cwl, gCwl);

    cudaFuncSetAttribute(gemm_mma<EP_NONE, false>,    cudaFuncAttributeMaxDynamicSharedMemorySize, GEMM_SMEM);
    cudaFuncSetAttribute(gemm_mma<EP_ACCUM, true>,    cudaFuncAttributeMaxDynamicSharedMemorySize, GEMM_SMEM);
    cudaFuncSetAttribute(gemm_mma<EP_MUL_SILU, true>, cudaFuncAttributeMaxDynamicSharedMemorySize, GEMM_SMEM);
    cudaFuncSetAttribute(gemm_mma<EP_ADD_AUX, false>, cudaFuncAttributeMaxDynamicSharedMemorySize, GEMM_SMEM);

    const dim3 blk(256);
    const dim3 gD(DM / 128, MROWS / 128);   // N=1024 -> (8,128)
    const dim3 gH(DH / 128, MROWS / 128);   // N=2048 -> (16,128)

    // Launch order arranged so index 5 is a full gH GEMM (ncu -s 5 -c 1 captures it).
    // 0) cvt x
    launch_cvt(x,  xh,  xl,  SZ_D);
    // 1) cvt w1
    launch_cvt(w1, w1h, w1l, (size_t)DM * DM);
    // 2) x1 = x @ w1^T
    gemm_mma<EP_NONE, false><<<gD, blk, GEMM_SMEM>>>(xh, xl, w1h, w1l, nullptr, nullptr,
                                                     x1, nullptr, nullptr, MROWS, DM, DM);
    // 3) xc = silu(conv(x1)+b)  -> bf16 planes
    {
        size_t n = SZ_D;
        conv_silu_bf16<<<(unsigned)((n + 255) / 256), 256>>>(x1, conv_w, conv_b, xch, xcl);
    }
    // 4) cvt dl_w
    launch_cvt(dl_w, dlh, dll, (size_t)DH * DM);
    // 5) dl GEMM  <-- ncu capture target
    gemm_mma<EP_NONE, false><<<gH, blk, GEMM_SMEM>>>(xch, xcl, dlh, dll, dl_b, nullptr,
                                                     h1, nullptr, nullptr, MROWS, DH, DM);
    // A_t
    launch_cvt(A_w, Awh, Awl, (size_t)DH * DM);
    gemm_mma<EP_NONE, false><<<gH, blk, GEMM_SMEM>>>(xch, xcl, Awh, Awl, A_b, nullptr,
                                                     h2, nullptr, nullptr, MROWS, DH, DM);
    // B_x
    launch_cvt(B_w, Bwh, Bwl, (size_t)DH * DM);
    gemm_mma<EP_NONE, false><<<gH, blk, GEMM_SMEM>>>(xch, xcl, Bwh, Bwl, B_b, nullptr,
                                                     h3, nullptr, nullptr, MROWS, DH, DM);
    // ssm = xc @ D_w^T + D_b   (before C-GEMM so it can accumulate)
    launch_cvt(D_w, Dwh, Dwl, (size_t)DM * DM);
    gemm_mma<EP_NONE, false><<<gD, blk, GEMM_SMEM>>>(xch, xcl, Dwh, Dwl, D_b, nullptr,
                                                     ssm, nullptr, nullptr, MROWS, DM, DM);
    // A_bar
    {
        size_t n = SZ_H;
        abar_kernel<<<(unsigned)((n + 255) / 256), 256>>>(h1, h2);
    }
    // chunked scan -> h bf16 planes
    {
        const int tot = BD * NCHK * DH;
        scan_p1<<<(tot + 255) / 256, 256>>>(h1, h3, Pc, Qc);
        scan_p2<<<(BD * DH + 255) / 256, 256>>>(Pc, Qc);
        scan_p3<<<(tot + 255) / 256, 256>>>(h1, h3, Pc, Qc, hh, hl);
    }
    // ssm += h @ C_w^T + C_b   (emit ssm bf16 planes)
    launch_cvt(C_w, Cwh, Cwl, (size_t)DM * DH);
    gemm_mma<EP_ACCUM, true><<<gD, blk, GEMM_SMEM>>>(hh, hl, Cwh, Cwl, C_b, nullptr,
                                                     ssm, sh, sl, MROWS, DM, DH);
    // z = ssm * silu(ssm @ w2^T)  (emit z bf16 planes)
    launch_cvt(w2, w2h, w2l, (size_t)DM * DM);
    gemm_mma<EP_MUL_SILU, true><<<gD, blk, GEMM_SMEM>>>(sh, sl, w2h, w2l, nullptr, ssm,
                                                        z, zh, zl, MROWS, DM, DM);
    // out = ssm + z @ w3^T
    launch_cvt(w3, w3h, w3l, (size_t)DM * DM);
    gemm_mma<EP_ADD_AUX, false><<<gD, blk, GEMM_SMEM>>>(zh, zl, w3h, w3l, nullptr, ssm,
                                                        out, nullptr, nullptr, MROWS, DM, DM);
}

// round 11
// speedup vs baseline: 2.8916x; 1.0500x over previous
#include <cuda_runtime.h>
#include <cuda_bf16.h>
#include <math.h>
#include <stdint.h>

// Problem dims (fixed by the dataset)
#define BD   4
#define LSEQ 4096
#define DM   1024
#define DH   2048
#define MROWS (BD * LSEQ)   // 16384
#define NCHK 64
#define LCHK 64             // NCHK*LCHK == LSEQ

static constexpr size_t SZ_D = (size_t)MROWS * DM;   // 16.78M
static constexpr size_t SZ_H = (size_t)MROWS * DH;   // 33.55M

// ---------------- scratch (no allocations allowed) ----------------
__device__ float g_x1 [SZ_D];
__device__ float g_h1 [SZ_H];   // dl pre-activation
__device__ float g_h2 [SZ_H];   // A_t
__device__ float g_h3 [SZ_H];   // B_x
__device__ float g_ssm[SZ_D];
__device__ float g_z  [SZ_D];
// scan carries: [BD][NCHK][DH]
__device__ float g_P [(size_t)BD * NCHK * DH];
__device__ float g_Q [(size_t)BD * NCHK * DH];

// bf16 hi/lo planes for activations
__device__ uint16_t gxh [SZ_D], gxl [SZ_D];
__device__ uint16_t gxch[SZ_D], gxcl[SZ_D];
__device__ uint16_t ghh [SZ_H], ghl [SZ_H];
__device__ uint16_t gsh [SZ_D], gsl [SZ_D];
__device__ uint16_t gzh [SZ_D], gzl [SZ_D];
// weights hi/lo
__device__ uint16_t gw1h[DM * DM], gw1l[DM * DM];
__device__ uint16_t gw2h[DM * DM], gw2l[DM * DM];
__device__ uint16_t gw3h[DM * DM], gw3l[DM * DM];
__device__ uint16_t gDwh[DM * DM], gDwl[DM * DM];
__device__ uint16_t gAwh[DH * DM], gAwl[DH * DM];
__device__ uint16_t gBwh[DH * DM], gBwl[DH * DM];
__device__ uint16_t gdlh[DH * DM], gdll[DH * DM];
__device__ uint16_t gCwh[DM * DH], gCwl[DM * DH];

__device__ __forceinline__ float siluf(float x) { return x / (1.0f + __expf(-x)); }
__device__ __forceinline__ float softplusf(float x) {
    return (x > 15.0f) ? x : __logf(1.0f + __expf(x));
}

__device__ __forceinline__ uint32_t smem_u32(const void* p) {
    uint32_t a;
    asm("{ .reg .u64 t; cvta.to.shared.u64 t, %1; cvt.u32.u64 %0, t; }" : "=r"(a) : "l"(p));
    return a;
}

#define CP_ASYNC16(s, g) \
    asm volatile("cp.async.cg.shared.global [%0], [%1], 16;" :: "r"(s), "l"(g) : "memory")
#define CP_COMMIT() asm volatile("cp.async.commit_group;" ::: "memory")
#define CP_WAIT1()  asm volatile("cp.async.wait_group 1;" ::: "memory")
#define CP_WAIT0()  asm volatile("cp.async.wait_group 0;" ::: "memory")

__device__ __forceinline__ void ldsm4(uint32_t* r, uint32_t addr) {
    asm volatile("ldmatrix.sync.aligned.m8n8.x4.shared.b16 {%0,%1,%2,%3}, [%4];"
                 : "=r"(r[0]), "=r"(r[1]), "=r"(r[2]), "=r"(r[3]) : "r"(addr));
}

__device__ __forceinline__ void mma_bf16(float* c, const uint32_t* a, const uint32_t* b) {
    asm volatile(
        "mma.sync.aligned.m16n8k16.row.col.f32.bf16.bf16.f32 "
        "{%0,%1,%2,%3}, {%4,%5,%6,%7}, {%8,%9}, {%0,%1,%2,%3};"
        : "+f"(c[0]), "+f"(c[1]), "+f"(c[2]), "+f"(c[3])
        : "r"(a[0]), "r"(a[1]), "r"(a[2]), "r"(a[3]), "r"(b[0]), "r"(b[1]));
}

__device__ __forceinline__ uint16_t bf16h(float x) {
    return __bfloat16_as_ushort(__float2bfloat16(x));
}
__device__ __forceinline__ float bf16f(uint16_t u) {
    return __bfloat162float(__ushort_as_bfloat16(u));
}
// split 4 floats -> packed hi/lo uint2
__device__ __forceinline__ void split4(const float* v, uint2& hp, uint2& lp) {
    uint16_t h0 = bf16h(v[0]), h1 = bf16h(v[1]), h2 = bf16h(v[2]), h3 = bf16h(v[3]);
    uint16_t l0 = bf16h(v[0] - bf16f(h0));
    uint16_t l1 = bf16h(v[1] - bf16f(h1));
    uint16_t l2 = bf16h(v[2] - bf16f(h2));
    uint16_t l3 = bf16h(v[3] - bf16f(h3));
    hp.x = ((uint32_t)h1 << 16) | h0; hp.y = ((uint32_t)h3 << 16) | h2;
    lp.x = ((uint32_t)l1 << 16) | l0; lp.y = ((uint32_t)l3 << 16) | l2;
}

// ===================== bf16-split GEMM on mma.sync =====================
enum { EP_NONE = 0, EP_ACCUM = 1, EP_MUL_SILU = 2, EP_ADD_AUX = 3 };

static constexpr int RS    = 80;           // padded SMEM row stride (bytes)
static constexpr int PLANE = 128 * RS;     // 10240
static constexpr int STG   = 4 * PLANE;    // 40960 (Ahi|Alo|Bhi|Blo)
static constexpr int NSTG  = 2;
static constexpr int GEMM_SMEM = NSTG * STG;   // 81920 -> 2 CTAs/SM

template <int EP, bool EMIT>
__global__ __launch_bounds__(256, 2) void gemm_mma(
    const uint16_t* __restrict__ Ah, const uint16_t* __restrict__ Al,
    const uint16_t* __restrict__ Bh, const uint16_t* __restrict__ Bl,
    const float* __restrict__ bias, const float* __restrict__ aux,
    float* __restrict__ C, uint16_t* __restrict__ Ch, uint16_t* __restrict__ Cl,
    int M, int N, int K)
{
    extern __shared__ char smem[];
    const uint32_t sb = smem_u32(smem);
    const int tid = threadIdx.x;
    const int wid = tid >> 5, l = tid & 31;
    const int warp_m = (wid >> 2) * 64;
    const int warp_n = (wid & 3) * 32;
    const int mtile = blockIdx.y, ntile = blockIdx.x;
    const int nch = K >> 5;

    const int ld_row = tid >> 2;
    const int ld_ch  = tid & 3;
    const size_t arow = (size_t)mtile * 128;
    const size_t brow = (size_t)ntile * 128;

    auto load_stage = [&](int s, int c) {
        const uint32_t st = sb + s * STG;
        const size_t kc = (size_t)c << 5;
        const uint16_t* gp0 = Ah + (arow + ld_row) * (size_t)K + kc + ld_ch * 8;
        const uint16_t* gp1 = Al + (arow + ld_row) * (size_t)K + kc + ld_ch * 8;
        const uint16_t* gp2 = Bh + (brow + ld_row) * (size_t)K + kc + ld_ch * 8;
        const uint16_t* gp3 = Bl + (brow + ld_row) * (size_t)K + kc + ld_ch * 8;
        const uint32_t s0 = st + ld_row * RS + ld_ch * 16;
        const size_t stp = (size_t)64 * K;
        CP_ASYNC16(s0,                   gp0);
        CP_ASYNC16(s0 + 64 * RS,         gp0 + stp);
        CP_ASYNC16(s0 + PLANE,           gp1);
        CP_ASYNC16(s0 + PLANE + 64*RS,   gp1 + stp);
        CP_ASYNC16(s0 + 2*PLANE,         gp2);
        CP_ASYNC16(s0 + 2*PLANE + 64*RS, gp2 + stp);
        CP_ASYNC16(s0 + 3*PLANE,         gp3);
        CP_ASYNC16(s0 + 3*PLANE + 64*RS, gp3 + stp);
    };

    const uint32_t aL = sb + (uint32_t)((warp_m + (l & 7) + ((l >> 3) & 1) * 8) * RS + (l >> 4) * 16);
    const uint32_t bL = sb + 2 * PLANE +
                        (uint32_t)((warp_n + (l & 7) + (l >> 4) * 8) * RS + ((l >> 3) & 1) * 16);

    float acc[4][4][4];
#pragma unroll
    for (int i = 0; i < 4; i++)
#pragma unroll
        for (int j = 0; j < 4; j++)
#pragma unroll
            for (int e = 0; e < 4; e++) acc[i][j][e] = 0.0f;

    load_stage(0, 0); CP_COMMIT();

    for (int c = 0; c < nch; ++c) {
        __syncthreads();   // prior reads of buffer (c+1)&1 complete
        if (c + 1 < nch) { load_stage((c + 1) & 1, c + 1); CP_COMMIT(); CP_WAIT1(); }
        else             { CP_WAIT0(); }
        __syncthreads();   // publish stage c

        const uint32_t so = (uint32_t)((c & 1) * STG);
#pragma unroll
        for (int ks = 0; ks < 2; ++ks) {
            const uint32_t ao = aL + so + ks * 32;
            const uint32_t bo = bL + so + ks * 32;
            uint32_t afh[4][4], afl[4][4], bfh[4][2], bfl[4][2];
#pragma unroll
            for (int mt = 0; mt < 4; ++mt) {
                ldsm4(afh[mt], ao + mt * 16 * RS);
                ldsm4(afl[mt], ao + PLANE + mt * 16 * RS);
            }
#pragma unroll
            for (int j = 0; j < 2; ++j) {
                uint32_t t[4];
                ldsm4(t, bo + j * 16 * RS);
                bfh[2*j][0] = t[0]; bfh[2*j][1] = t[1];
                bfh[2*j+1][0] = t[2]; bfh[2*j+1][1] = t[3];
                ldsm4(t, bo + PLANE + j * 16 * RS);
                bfl[2*j][0] = t[0]; bfl[2*j][1] = t[1];
                bfl[2*j+1][0] = t[2]; bfl[2*j+1][1] = t[3];
            }
#pragma unroll
            for (int mt = 0; mt < 4; ++mt)
#pragma unroll
                for (int nt = 0; nt < 4; ++nt) {
                    mma_bf16(acc[mt][nt], afh[mt], bfh[nt]);
                    mma_bf16(acc[mt][nt], afh[mt], bfl[nt]);
                    mma_bf16(acc[mt][nt], afl[mt], bfh[nt]);
                }
        }
    }

    // epilogue
    const int mrow0 = mtile * 128 + warp_m + (l >> 2);
    const int coln0 = ntile * 128 + warp_n + (l & 3) * 2;
#pragma unroll
    for (int mt = 0; mt < 4; ++mt) {
#pragma unroll
        for (int nt = 0; nt < 4; ++nt) {
            const int col = coln0 + nt * 8;
#pragma unroll
            for (int h = 0; h < 2; ++h) {
                const int row = mrow0 + mt * 16 + h * 8;
                float v0 = acc[mt][nt][h * 2 + 0];
                float v1 = acc[mt][nt][h * 2 + 1];
                if (bias) { v0 += bias[col]; v1 += bias[col + 1]; }
                const size_t idx = (size_t)row * N + col;
                if (EP == EP_ACCUM) {
                    float2 cv = *reinterpret_cast<const float2*>(&C[idx]);
                    v0 += cv.x; v1 += cv.y;
                } else if (EP == EP_MUL_SILU) {
                    float2 av = *reinterpret_cast<const float2*>(&aux[idx]);
                    v0 = av.x * siluf(v0); v1 = av.y * siluf(v1);
                } else if (EP == EP_ADD_AUX) {
                    float2 av = *reinterpret_cast<const float2*>(&aux[idx]);
                    v0 = av.x + v0; v1 = av.y + v1;
                }
                float2 ov; ov.x = v0; ov.y = v1;
                *reinterpret_cast<float2*>(&C[idx]) = ov;
                if (EMIT) {
                    uint16_t h0 = bf16h(v0), h1 = bf16h(v1);
                    uint16_t l0 = bf16h(v0 - bf16f(h0)), l1 = bf16h(v1 - bf16f(h1));
                    *reinterpret_cast<uint32_t*>(&Ch[idx]) = ((uint32_t)h1 << 16) | h0;
                    *reinterpret_cast<uint32_t*>(&Cl[idx]) = ((uint32_t)l1 << 16) | l0;
                }
            }
        }
    }
}

// -------------- fp32 -> bf16 hi/lo split (x input) --------------------------
__global__ void cvt_split(const float* __restrict__ x, uint16_t* __restrict__ hi,
                          uint16_t* __restrict__ lo, size_t n4)
{
    size_t i = (size_t)blockIdx.x * blockDim.x + threadIdx.x;
    if (i >= n4) return;
    float4 v = reinterpret_cast<const float4*>(x)[i];
    uint2 hp, lp; split4(&v.x, hp, lp);
    reinterpret_cast<uint2*>(hi)[i] = hp;
    reinterpret_cast<uint2*>(lo)[i] = lp;
}

// -------------- batched weight conversions (8 tensors, one launch) ----------
struct CvtPack {
    const float* src[8];
    uint16_t* hi[8];
    uint16_t* lo[8];
};
// regions 0-3: DM*DM (2^18 float4 each); regions 4-7: DH*DM (2^19 float4 each)
static constexpr unsigned CVT8_N4 = (4u << 18) + (4u << 19);   // 3145728

__global__ void cvt_split8(CvtPack p)
{
    unsigned i = blockIdx.x * blockDim.x + threadIdx.x;
    if (i >= CVT8_N4) return;
    unsigned r, off;
    if (i < (4u << 18)) { r = i >> 18;              off = i & ((1u << 18) - 1); }
    else { unsigned j = i - (4u << 18); r = 4 + (j >> 19); off = j & ((1u << 19) - 1); }
    float4 v = reinterpret_cast<const float4*>(p.src[r])[off];
    uint2 hp, lp; split4(&v.x, hp, lp);
    reinterpret_cast<uint2*>(p.hi[r])[off] = hp;
    reinterpret_cast<uint2*>(p.lo[r])[off] = lp;
}

// -------------- depthwise conv1d (k=3, pad=1) + bias + SiLU (vec4) ----------
__global__ void conv_silu_bf16_v4(const float* __restrict__ x,
                                  const float* __restrict__ w, const float* __restrict__ b,
                                  uint16_t* __restrict__ yh, uint16_t* __restrict__ yl)
{
    size_t i4 = (size_t)blockIdx.x * blockDim.x + threadIdx.x;
    const size_t n4 = SZ_D / 4;
    if (i4 >= n4) return;
    const size_t idx = i4 * 4;
    const int d = (int)(idx % DM);
    const int t = (int)((idx / DM) % LSEQ);

    float4 xc = *reinterpret_cast<const float4*>(x + idx);
    float4 xm = make_float4(0.f, 0.f, 0.f, 0.f);
    float4 xp = make_float4(0.f, 0.f, 0.f, 0.f);
    if (t > 0)        xm = *reinterpret_cast<const float4*>(x + idx - DM);
    if (t < LSEQ - 1) xp = *reinterpret_cast<const float4*>(x + idx + DM);
    // 12 consecutive conv weights for channels d..d+3 ([D,1,3] layout)
    float4 wA = *reinterpret_cast<const float4*>(w + (size_t)d * 3);
    float4 wB = *reinterpret_cast<const float4*>(w + (size_t)d * 3 + 4);
    float4 wC = *reinterpret_cast<const float4*>(w + (size_t)d * 3 + 8);
    const float wf[12] = {wA.x, wA.y, wA.z, wA.w, wB.x, wB.y, wB.z, wB.w,
                          wC.x, wC.y, wC.z, wC.w};
    float4 bb = *reinterpret_cast<const float4*>(b + d);
    const float xmv[4] = {xm.x, xm.y, xm.z, xm.w};
    const float xcv[4] = {xc.x, xc.y, xc.z, xc.w};
    const float xpv[4] = {xp.x, xp.y, xp.z, xp.w};
    const float bv[4]  = {bb.x, bb.y, bb.z, bb.w};
    float out[4];
#pragma unroll
    for (int k = 0; k < 4; ++k) {
        float s = bv[k];
        s = fmaf(wf[k * 3 + 0], xmv[k], s);
        s = fmaf(wf[k * 3 + 1], xcv[k], s);
        s = fmaf(wf[k * 3 + 2], xpv[k], s);
        out[k] = siluf(s);
    }
    uint2 hp, lp; split4(out, hp, lp);
    reinterpret_cast<uint2*>(yh)[i4] = hp;
    reinterpret_cast<uint2*>(yl)[i4] = lp;
}

// -------------- chunked scan, abar fused (vec4 across channels) -------------
// abar = exp(-softplus(dl) * At), computed on the fly from h1 (dl) and h2 (At).
__device__ __forceinline__ float abar_of(float dl, float at) {
    return __expf(-softplusf(dl) * at);
}

__global__ void scan_p1_v4(const float* __restrict__ DL, const float* __restrict__ AT,
                           const float* __restrict__ BX,
                           float* __restrict__ P, float* __restrict__ Q)
{
    unsigned i = blockIdx.x * blockDim.x + threadIdx.x;     // vec4 index
    const unsigned tot4 = (unsigned)(BD * NCHK * DH / 4);
    if (i >= tot4) return;
    const unsigned idx = i * 4;
    const int hc = (int)(idx % DH);
    const int c  = (int)((idx / DH) % NCHK);
    const int b  = (int)(idx / (DH * NCHK));
    const size_t base = ((size_t)b * LSEQ + (size_t)c * LCHK) * DH + hc;
    float a[4] = {1.f, 1.f, 1.f, 1.f}, q[4] = {0.f, 0.f, 0.f, 0.f};
#pragma unroll 2
    for (int t = 0; t < LCHK; ++t) {
        const size_t off = base + (size_t)t * DH;
        float4 dl = *reinterpret_cast<const float4*>(DL + off);
        float4 at = *reinterpret_cast<const float4*>(AT + off);
        float4 bx = *reinterpret_cast<const float4*>(BX + off);
        const float dlv[4] = {dl.x, dl.y, dl.z, dl.w};
        const float atv[4] = {at.x, at.y, at.z, at.w};
        const float bxv[4] = {bx.x, bx.y, bx.z, bx.w};
#pragma unroll
        for (int k = 0; k < 4; ++k) {
            a[k] *= abar_of(dlv[k], atv[k]);
            q[k] = fmaf(bxv[k], a[k], q[k]);
        }
    }
    const size_t ci = ((size_t)b * NCHK + c) * DH + hc;
    *reinterpret_cast<float4*>(P + ci) = make_float4(a[0], a[1], a[2], a[3]);
    *reinterpret_cast<float4*>(Q + ci) = make_float4(q[0], q[1], q[2], q[3]);
}

__global__ void scan_p2_v4(float* __restrict__ P, float* __restrict__ Q)
{
    unsigned i = blockIdx.x * blockDim.x + threadIdx.x;     // vec4 channel index
    const unsigned tot4 = (unsigned)(BD * DH / 4);
    if (i >= tot4) return;
    const unsigned idx = i * 4;
    const int b  = (int)(idx / DH);
    const int hc = (int)(idx % DH);
    float a[4] = {1.f, 1.f, 1.f, 1.f}, s[4] = {0.f, 0.f, 0.f, 0.f};
    for (int c = 0; c < NCHK; ++c) {
        const size_t ci = ((size_t)b * NCHK + c) * DH + hc;
        float4 tp = *reinterpret_cast<float4*>(P + ci);
        float4 tq = *reinterpret_cast<float4*>(Q + ci);
        *reinterpret_cast<float4*>(P + ci) = make_float4(a[0], a[1], a[2], a[3]);
        *reinterpret_cast<float4*>(Q + ci) = make_float4(s[0], s[1], s[2], s[3]);
        const float tpv[4] = {tp.x, tp.y, tp.z, tp.w};
        const float tqv[4] = {tq.x, tq.y, tq.z, tq.w};
#pragma unroll
        for (int k = 0; k < 4; ++k) {
            s[k] = fmaf(a[k], tqv[k], s[k]);
            a[k] *= tpv[k];
        }
    }
}

__global__ void scan_p3_v4(const float* __restrict__ DL, const float* __restrict__ AT,
                           const float* __restrict__ BX,
                           const float* __restrict__ Ain, const float* __restrict__ Sin,
                           uint16_t* __restrict__ hh, uint16_t* __restrict__ hl)
{
    unsigned i = blockIdx.x * blockDim.x + threadIdx.x;
    const unsigned tot4 = (unsigned)(BD * NCHK * DH / 4);
    if (i >= tot4) return;
    const unsigned idx = i * 4;
    const int hc = (int)(idx % DH);
    const int c  = (int)((idx / DH) % NCHK);
    const int b  = (int)(idx / (DH * NCHK));
    const size_t base = ((size_t)b * LSEQ + (size_t)c * LCHK) * DH + hc;
    const size_t ci = ((size_t)b * NCHK + c) * DH + hc;
    float4 a4 = *reinterpret_cast<const float4*>(Ain + ci);
    float4 s4 = *reinterpret_cast<const float4*>(Sin + ci);
    float a[4] = {a4.x, a4.y, a4.z, a4.w};
    float s[4] = {s4.x, s4.y, s4.z, s4.w};
#pragma unroll 2
    for (int t = 0; t < LCHK; ++t) {
        const size_t off = base + (size_t)t * DH;
        float4 dl = *reinterpret_cast<const float4*>(DL + off);
        float4 at = *reinterpret_cast<const float4*>(AT + off);
        float4 bx = *reinterpret_cast<const float4*>(BX + off);
        const float dlv[4] = {dl.x, dl.y, dl.z, dl.w};
        const float atv[4] = {at.x, at.y, at.z, at.w};
        const float bxv[4] = {bx.x, bx.y, bx.z, bx.w};
#pragma unroll
        for (int k = 0; k < 4; ++k) {
            a[k] *= abar_of(dlv[k], atv[k]);
            s[k] = fmaf(bxv[k], a[k], s[k]);
        }
        uint2 hp, lp; split4(s, hp, lp);
        reinterpret_cast<uint2*>(hh)[off / 4] = hp;
        reinterpret_cast<uint2*>(hl)[off / 4] = lp;
    }
}

// ---------------------------------------------------------------------------
extern "C" void kernel_launch(void* const* d_in, const int* in_sizes, int n_in,
                              void* d_out, int out_size)
{
    const float* x      = (const float*)d_in[0];
    const float* w1     = (const float*)d_in[1];
    const float* w2     = (const float*)d_in[2];
    const float* w3     = (const float*)d_in[3];
    const float* conv_w = (const float*)d_in[4];
    const float* conv_b = (const float*)d_in[5];
    const float* A_w    = (const float*)d_in[6];
    const float* A_b    = (const float*)d_in[7];
    const float* B_w    = (const float*)d_in[8];
    const float* B_b    = (const float*)d_in[9];
    const float* C_w    = (const float*)d_in[10];
    const float* C_b    = (const float*)d_in[11];
    const float* D_w    = (const float*)d_in[12];
    const float* D_b    = (const float*)d_in[13];
    const float* dl_w   = (const float*)d_in[14];
    const float* dl_b   = (const float*)d_in[15];
    float* out = (float*)d_out;

    float *x1, *h1, *h2, *h3, *ssm, *z, *Pc, *Qc;
    uint16_t *xh, *xl, *xch, *xcl, *hh, *hl, *sh, *sl, *zh, *zl;
    uint16_t *w1h, *w1l, *w2h, *w2l, *w3h, *w3l, *Dwh, *Dwl;
    uint16_t *Awh, *Awl, *Bwh, *Bwl, *dlh, *dll, *Cwh, *Cwl;
    cudaGetSymbolAddress((void**)&x1,  g_x1);
    cudaGetSymbolAddress((void**)&h1,  g_h1);
    cudaGetSymbolAddress((void**)&h2,  g_h2);
    cudaGetSymbolAddress((void**)&h3,  g_h3);
    cudaGetSymbolAddress((void**)&ssm, g_ssm);
    cudaGetSymbolAddress((void**)&z,   g_z);
    cudaGetSymbolAddress((void**)&Pc,  g_P);
    cudaGetSymbolAddress((void**)&Qc,  g_Q);
    cudaGetSymbolAddress((void**)&xh,  gxh);  cudaGetSymbolAddress((void**)&xl,  gxl);
    cudaGetSymbolAddress((void**)&xch, gxch); cudaGetSymbolAddress((void**)&xcl, gxcl);
    cudaGetSymbolAddress((void**)&hh,  ghh);  cudaGetSymbolAddress((void**)&hl,  ghl);
    cudaGetSymbolAddress((void**)&sh,  gsh);  cudaGetSymbolAddress((void**)&sl,  gsl);
    cudaGetSymbolAddress((void**)&zh,  gzh);  cudaGetSymbolAddress((void**)&zl,  gzl);
    cudaGetSymbolAddress((void**)&w1h, gw1h); cudaGetSymbolAddress((void**)&w1l, gw1l);
    cudaGetSymbolAddress((void**)&w2h, gw2h); cudaGetSymbolAddress((void**)&w2l, gw2l);
    cudaGetSymbolAddress((void**)&w3h, gw3h); cudaGetSymbolAddress((void**)&w3l, gw3l);
    cudaGetSymbolAddress((void**)&Dwh, gDwh); cudaGetSymbolAddress((void**)&Dwl, gDwl);
    cudaGetSymbolAddress((void**)&Awh, gAwh); cudaGetSymbolAddress((void**)&Awl, gAwl);
    cudaGetSymbolAddress((void**)&Bwh, gBwh); cudaGetSymbolAddress((void**)&Bwl, gBwl);
    cudaGetSymbolAddress((void**)&dlh, gdlh); cudaGetSymbolAddress((void**)&dll, gdll);
    cudaGetSymbolAddress((void**)&Cwh, gCwh); cudaGetSymbolAddress((void**)&Cwl, gCwl);

    cudaFuncSetAttribute(gemm_mma<EP_NONE, false>,    cudaFuncAttributeMaxDynamicSharedMemorySize, GEMM_SMEM);
    cudaFuncSetAttribute(gemm_mma<EP_ACCUM, true>,    cudaFuncAttributeMaxDynamicSharedMemorySize, GEMM_SMEM);
    cudaFuncSetAttribute(gemm_mma<EP_MUL_SILU, true>, cudaFuncAttributeMaxDynamicSharedMemorySize, GEMM_SMEM);
    cudaFuncSetAttribute(gemm_mma<EP_ADD_AUX, false>, cudaFuncAttributeMaxDynamicSharedMemorySize, GEMM_SMEM);

    const dim3 blk(256);
    const dim3 gD(DM / 128, MROWS / 128);   // N=1024 -> (8,128)
    const dim3 gH(DH / 128, MROWS / 128);   // N=2048 -> (16,128)

    // 0) cvt x
    {
        size_t n4 = SZ_D / 4;
        cvt_split<<<(unsigned)((n4 + 255) / 256), 256>>>(x, xh, xl, n4);
    }
    // 1) all 8 weight conversions in one launch
    {
        CvtPack p;
        p.src[0] = w1;  p.hi[0] = w1h; p.lo[0] = w1l;
        p.src[1] = w2;  p.hi[1] = w2h; p.lo[1] = w2l;
        p.src[2] = w3;  p.hi[2] = w3h; p.lo[2] = w3l;
        p.src[3] = D_w; p.hi[3] = Dwh; p.lo[3] = Dwl;
        p.src[4] = A_w; p.hi[4] = Awh; p.lo[4] = Awl;
        p.src[5] = B_w; p.hi[5] = Bwh; p.lo[5] = Bwl;
        p.src[6] = dl_w; p.hi[6] = dlh; p.lo[6] = dll;
        p.src[7] = C_w; p.hi[7] = Cwh; p.lo[7] = Cwl;
        cvt_split8<<<(CVT8_N4 + 255) / 256, 256>>>(p);
    }
    // 2) x1 = x @ w1^T
    gemm_mma<EP_NONE, false><<<gD, blk, GEMM_SMEM>>>(xh, xl, w1h, w1l, nullptr, nullptr,
                                                     x1, nullptr, nullptr, MROWS, DM, DM);
    // 3) xc = silu(conv(x1)+b) -> bf16 planes
    {
        size_t n4 = SZ_D / 4;
        conv_silu_bf16_v4<<<(unsigned)((n4 + 255) / 256), 256>>>(x1, conv_w, conv_b, xch, xcl);
    }
    // 4) dl GEMM
    gemm_mma<EP_NONE, false><<<gH, blk, GEMM_SMEM>>>(xch, xcl, dlh, dll, dl_b, nullptr,
                                                     h1, nullptr, nullptr, MROWS, DH, DM);
    // 5) A_t GEMM  <-- ncu -s 5 capture target
    gemm_mma<EP_NONE, false><<<gH, blk, GEMM_SMEM>>>(xch, xcl, Awh, Awl, A_b, nullptr,
                                                     h2, nullptr, nullptr, MROWS, DH, DM);
    // 6) B_x GEMM
    gemm_mma<EP_NONE, false><<<gH, blk, GEMM_SMEM>>>(xch, xcl, Bwh, Bwl, B_b, nullptr,
                                                     h3, nullptr, nullptr, MROWS, DH, DM);
    // 7) ssm = xc @ D_w^T + D_b
    gemm_mma<EP_NONE, false><<<gD, blk, GEMM_SMEM>>>(xch, xcl, Dwh, Dwl, D_b, nullptr,
                                                     ssm, nullptr, nullptr, MROWS, DM, DM);
    // 8-10) chunked scan with fused abar -> h bf16 planes
    {
        const unsigned tot4 = (unsigned)(BD * NCHK * DH / 4);
        scan_p1_v4<<<(tot4 + 255) / 256, 256>>>(h1, h2, h3, Pc, Qc);
        scan_p2_v4<<<((unsigned)(BD * DH / 4) + 255) / 256, 256>>>(Pc, Qc);
        scan_p3_v4<<<(tot4 + 255) / 256, 256>>>(h1, h2, h3, Pc, Qc, hh, hl);
    }
    // 11) ssm += h @ C_w^T + C_b   (emit ssm bf16 planes)
    gemm_mma<EP_ACCUM, true><<<gD, blk, GEMM_SMEM>>>(hh, hl, Cwh, Cwl, C_b, nullptr,
                                                     ssm, sh, sl, MROWS, DM, DH);
    // 12) z = ssm * silu(ssm @ w2^T)  (emit z bf16 planes)
    gemm_mma<EP_MUL_SILU, true><<<gD, blk, GEMM_SMEM>>>(sh, sl, w2h, w2l, nullptr, ssm,
                                                        z, zh, zl, MROWS, DM, DM);
    // 13) out = ssm + z @ w3^T
    gemm_mma<EP_ADD_AUX, false><<<gD, blk, GEMM_SMEM>>>(zh, zl, w3h, w3l, nullptr, ssm,
                                                        out, nullptr, nullptr, MROWS, DM, DM);
}

// round 12
// speedup vs baseline: 3.2826x; 1.1352x over previous
#include <cuda_runtime.h>
#include <cuda_bf16.h>
#include <math.h>
#include <stdint.h>

// Problem dims (fixed by the dataset)
#define BD   4
#define LSEQ 4096
#define DM   1024
#define DH   2048
#define MROWS (BD * LSEQ)   // 16384
#define NCHK 64
#define LCHK 64             // NCHK*LCHK == LSEQ

static constexpr size_t SZ_D = (size_t)MROWS * DM;   // 16.78M
static constexpr size_t SZ_H = (size_t)MROWS * DH;   // 33.55M

// ---------------- scratch (no allocations allowed) ----------------
__device__ float g_x1 [SZ_D];
__device__ float g_h1 [SZ_H];   // dl pre-activation
__device__ float g_h2 [SZ_H];   // A_t
__device__ float g_h3 [SZ_H];   // B_x
__device__ float g_ssm[SZ_D];
__device__ float g_z  [SZ_D];
// scan carries: [BD][NCHK][DH]
__device__ float g_P [(size_t)BD * NCHK * DH];
__device__ float g_Q [(size_t)BD * NCHK * DH];

// bf16 hi/lo planes for activations
__device__ uint16_t gxh [SZ_D], gxl [SZ_D];
__device__ uint16_t gxch[SZ_D], gxcl[SZ_D];
__device__ uint16_t ghh [SZ_H], ghl [SZ_H];
__device__ uint16_t gsh [SZ_D], gsl [SZ_D];
__device__ uint16_t gzh [SZ_D], gzl [SZ_D];
// weights hi/lo
__device__ uint16_t gw1h[DM * DM], gw1l[DM * DM];
__device__ uint16_t gw2h[DM * DM], gw2l[DM * DM];
__device__ uint16_t gw3h[DM * DM], gw3l[DM * DM];
__device__ uint16_t gDwh[DM * DM], gDwl[DM * DM];
__device__ uint16_t gAwh[DH * DM], gAwl[DH * DM];
__device__ uint16_t gBwh[DH * DM], gBwl[DH * DM];
__device__ uint16_t gdlh[DH * DM], gdll[DH * DM];
__device__ uint16_t gCwh[DM * DH], gCwl[DM * DH];

__device__ __forceinline__ float siluf(float x) { return x / (1.0f + __expf(-x)); }
__device__ __forceinline__ float softplusf(float x) {
    return (x > 15.0f) ? x : __logf(1.0f + __expf(x));
}

__device__ __forceinline__ uint32_t smem_u32(const void* p) {
    uint32_t a;
    asm("{ .reg .u64 t; cvta.to.shared.u64 t, %1; cvt.u32.u64 %0, t; }" : "=r"(a) : "l"(p));
    return a;
}

#define CP_ASYNC16(s, g) \
    asm volatile("cp.async.cg.shared.global [%0], [%1], 16;" :: "r"(s), "l"(g) : "memory")
#define CP_COMMIT() asm volatile("cp.async.commit_group;" ::: "memory")
#define CP_WAIT1()  asm volatile("cp.async.wait_group 1;" ::: "memory")
#define CP_WAIT0()  asm volatile("cp.async.wait_group 0;" ::: "memory")

__device__ __forceinline__ void ldsm4(uint32_t* r, uint32_t addr) {
    asm volatile("ldmatrix.sync.aligned.m8n8.x4.shared.b16 {%0,%1,%2,%3}, [%4];"
                 : "=r"(r[0]), "=r"(r[1]), "=r"(r[2]), "=r"(r[3]) : "r"(addr));
}

__device__ __forceinline__ void mma_bf16(float* c, const uint32_t* a, const uint32_t* b) {
    asm volatile(
        "mma.sync.aligned.m16n8k16.row.col.f32.bf16.bf16.f32 "
        "{%0,%1,%2,%3}, {%4,%5,%6,%7}, {%8,%9}, {%0,%1,%2,%3};"
        : "+f"(c[0]), "+f"(c[1]), "+f"(c[2]), "+f"(c[3])
        : "r"(a[0]), "r"(a[1]), "r"(a[2]), "r"(a[3]), "r"(b[0]), "r"(b[1]));
}

__device__ __forceinline__ uint16_t bf16h(float x) {
    return __bfloat16_as_ushort(__float2bfloat16(x));
}
__device__ __forceinline__ float bf16f(uint16_t u) {
    return __bfloat162float(__ushort_as_bfloat16(u));
}
__device__ __forceinline__ void split4(const float* v, uint2& hp, uint2& lp) {
    uint16_t h0 = bf16h(v[0]), h1 = bf16h(v[1]), h2 = bf16h(v[2]), h3 = bf16h(v[3]);
    uint16_t l0 = bf16h(v[0] - bf16f(h0));
    uint16_t l1 = bf16h(v[1] - bf16f(h1));
    uint16_t l2 = bf16h(v[2] - bf16f(h2));
    uint16_t l3 = bf16h(v[3] - bf16f(h3));
    hp.x = ((uint32_t)h1 << 16) | h0; hp.y = ((uint32_t)h3 << 16) | h2;
    lp.x = ((uint32_t)l1 << 16) | l0; lp.y = ((uint32_t)l3 << 16) | l2;
}

// SW64 swizzle for 64B rows: XOR 16B-group index (bits 5:4) with row bits (9:7)>>3
__device__ __forceinline__ uint32_t sw64(uint32_t off) { return off ^ ((off >> 3) & 0x30); }

// ===================== bf16-split GEMM on mma.sync =====================
// C[M,N] = A[M,K] @ B[N,K]^T. CTA 128x128, BK=32 bf16 (64B rows, SW64 swizzle),
// 3-stage cp.async ring, 8 warps @ 64x32, 2 CTAs/SM, 1 syncthreads per chunk.
enum { EP_NONE = 0, EP_ACCUM = 1, EP_MUL_SILU = 2, EP_ADD_AUX = 3 };

static constexpr int RS    = 64;           // SMEM row stride (bytes) — no pad, swizzled
static constexpr int PLANE = 128 * RS;     // 8192
static constexpr int STG   = 4 * PLANE;    // 32768 (Ahi|Alo|Bhi|Blo)
static constexpr int NSTG  = 3;
static constexpr int GEMM_SMEM = NSTG * STG;   // 98304 -> 2 CTAs/SM

template <int EP, bool EMIT>
__global__ __launch_bounds__(256, 2) void gemm_mma(
    const uint16_t* __restrict__ Ah, const uint16_t* __restrict__ Al,
    const uint16_t* __restrict__ Bh, const uint16_t* __restrict__ Bl,
    const float* __restrict__ bias, const float* __restrict__ aux,
    float* __restrict__ C, uint16_t* __restrict__ Ch, uint16_t* __restrict__ Cl,
    int M, int N, int K)
{
    extern __shared__ char smem[];
    const uint32_t sb = smem_u32(smem);
    const int tid = threadIdx.x;
    const int wid = tid >> 5, l = tid & 31;
    const int warp_m = (wid >> 2) * 64;
    const int warp_n = (wid & 3) * 32;
    const int mtile = blockIdx.y, ntile = blockIdx.x;
    const int nch = K >> 5;

    const int ld_row = tid >> 2;
    const int ld_ch  = tid & 3;
    const size_t arow = (size_t)mtile * 128;
    const size_t brow = (size_t)ntile * 128;
    // swizzled write offset within a plane (identical for rows r and r+64)
    const uint32_t woff = sw64((uint32_t)(ld_row * RS + ld_ch * 16));

    auto load_stage = [&](int s, int c) {
        const uint32_t st = sb + s * STG;
        const size_t kc = (size_t)c << 5;
        const uint16_t* gp0 = Ah + (arow + ld_row) * (size_t)K + kc + ld_ch * 8;
        const uint16_t* gp1 = Al + (arow + ld_row) * (size_t)K + kc + ld_ch * 8;
        const uint16_t* gp2 = Bh + (brow + ld_row) * (size_t)K + kc + ld_ch * 8;
        const uint16_t* gp3 = Bl + (brow + ld_row) * (size_t)K + kc + ld_ch * 8;
        const uint32_t s0 = st + woff;
        const size_t stp = (size_t)64 * K;
        CP_ASYNC16(s0,                  gp0);
        CP_ASYNC16(s0 + 4096,           gp0 + stp);   // +64 rows
        CP_ASYNC16(s0 + PLANE,          gp1);
        CP_ASYNC16(s0 + PLANE + 4096,   gp1 + stp);
        CP_ASYNC16(s0 + 2*PLANE,        gp2);
        CP_ASYNC16(s0 + 2*PLANE + 4096, gp2 + stp);
        CP_ASYNC16(s0 + 3*PLANE,        gp3);
        CP_ASYNC16(s0 + 3*PLANE + 4096, gp3 + stp);
    };

    // ldmatrix lane base addresses (swizzled; stage offset added per use).
    // ks (K-half) toggles logical 16B-group bit1 -> XOR 32 in swizzled space.
    const int arow_l = warp_m + (l & 7) + ((l >> 3) & 1) * 8;
    const uint32_t aL = sb + sw64((uint32_t)(arow_l * RS + (l >> 4) * 16));
    const int brow_l = warp_n + (l & 7) + (l >> 4) * 8;
    const uint32_t bL = sb + 2 * PLANE + sw64((uint32_t)(brow_l * RS + ((l >> 3) & 1) * 16));

    float acc[4][4][4];
#pragma unroll
    for (int i = 0; i < 4; i++)
#pragma unroll
        for (int j = 0; j < 4; j++)
#pragma unroll
            for (int e = 0; e < 4; e++) acc[i][j][e] = 0.0f;

    load_stage(0, 0); CP_COMMIT();
    load_stage(1, 1); CP_COMMIT();

    int sidx = 0;   // stage of chunk c
    for (int c = 0; c < nch; ++c) {
        if (c + 1 < nch) CP_WAIT1(); else CP_WAIT0();
        __syncthreads();            // stage c visible CTA-wide; stage (c-1) reads done
        if (c + 2 < nch) {
            int s2 = sidx + 2; if (s2 >= NSTG) s2 -= NSTG;
            load_stage(s2, c + 2);  // overwrites buffer of chunk c-1
            CP_COMMIT();
        }

        const uint32_t so = (uint32_t)(sidx * STG);
#pragma unroll
        for (int ks = 0; ks < 2; ++ks) {
            const uint32_t ao = (aL + so) ^ (ks << 5);
            const uint32_t bo = (bL + so) ^ (ks << 5);
            uint32_t afh[4][4], afl[4][4], bfh[4][2], bfl[4][2];
#pragma unroll
            for (int mt = 0; mt < 4; ++mt) {
                ldsm4(afh[mt], ao + mt * 16 * RS);
                ldsm4(afl[mt], ao + PLANE + mt * 16 * RS);
            }
#pragma unroll
            for (int j = 0; j < 2; ++j) {
                uint32_t t[4];
                ldsm4(t, bo + j * 16 * RS);
                bfh[2*j][0] = t[0]; bfh[2*j][1] = t[1];
                bfh[2*j+1][0] = t[2]; bfh[2*j+1][1] = t[3];
                ldsm4(t, bo + PLANE + j * 16 * RS);
                bfl[2*j][0] = t[0]; bfl[2*j][1] = t[1];
                bfl[2*j+1][0] = t[2]; bfl[2*j+1][1] = t[3];
            }
#pragma unroll
            for (int mt = 0; mt < 4; ++mt)
#pragma unroll
                for (int nt = 0; nt < 4; ++nt) {
                    mma_bf16(acc[mt][nt], afh[mt], bfh[nt]);
                    mma_bf16(acc[mt][nt], afh[mt], bfl[nt]);
                    mma_bf16(acc[mt][nt], afl[mt], bfh[nt]);
                }
        }
        if (++sidx == NSTG) sidx = 0;
    }

    // epilogue
    const int mrow0 = mtile * 128 + warp_m + (l >> 2);
    const int coln0 = ntile * 128 + warp_n + (l & 3) * 2;
#pragma unroll
    for (int mt = 0; mt < 4; ++mt) {
#pragma unroll
        for (int nt = 0; nt < 4; ++nt) {
            const int col = coln0 + nt * 8;
#pragma unroll
            for (int h = 0; h < 2; ++h) {
                const int row = mrow0 + mt * 16 + h * 8;
                float v0 = acc[mt][nt][h * 2 + 0];
                float v1 = acc[mt][nt][h * 2 + 1];
                if (bias) { v0 += bias[col]; v1 += bias[col + 1]; }
                const size_t idx = (size_t)row * N + col;
                if (EP == EP_ACCUM) {
                    float2 cv = *reinterpret_cast<const float2*>(&C[idx]);
                    v0 += cv.x; v1 += cv.y;
                } else if (EP == EP_MUL_SILU) {
                    float2 av = *reinterpret_cast<const float2*>(&aux[idx]);
                    v0 = av.x * siluf(v0); v1 = av.y * siluf(v1);
                } else if (EP == EP_ADD_AUX) {
                    float2 av = *reinterpret_cast<const float2*>(&aux[idx]);
                    v0 = av.x + v0; v1 = av.y + v1;
                }
                float2 ov; ov.x = v0; ov.y = v1;
                *reinterpret_cast<float2*>(&C[idx]) = ov;
                if (EMIT) {
                    uint16_t h0 = bf16h(v0), h1 = bf16h(v1);
                    uint16_t l0 = bf16h(v0 - bf16f(h0)), l1 = bf16h(v1 - bf16f(h1));
                    *reinterpret_cast<uint32_t*>(&Ch[idx]) = ((uint32_t)h1 << 16) | h0;
                    *reinterpret_cast<uint32_t*>(&Cl[idx]) = ((uint32_t)l1 << 16) | l0;
                }
            }
        }
    }
}

// -------------- fp32 -> bf16 hi/lo split (x input) --------------------------
__global__ void cvt_split(const float* __restrict__ x, uint16_t* __restrict__ hi,
                          uint16_t* __restrict__ lo, size_t n4)
{
    size_t i = (size_t)blockIdx.x * blockDim.x + threadIdx.x;
    if (i >= n4) return;
    float4 v = reinterpret_cast<const float4*>(x)[i];
    uint2 hp, lp; split4(&v.x, hp, lp);
    reinterpret_cast<uint2*>(hi)[i] = hp;
    reinterpret_cast<uint2*>(lo)[i] = lp;
}

// -------------- batched weight conversions (8 tensors, one launch) ----------
struct CvtPack {
    const float* src[8];
    uint16_t* hi[8];
    uint16_t* lo[8];
};
static constexpr unsigned CVT8_N4 = (4u << 18) + (4u << 19);   // 3145728

__global__ void cvt_split8(CvtPack p)
{
    unsigned i = blockIdx.x * blockDim.x + threadIdx.x;
    if (i >= CVT8_N4) return;
    unsigned r, off;
    if (i < (4u << 18)) { r = i >> 18;              off = i & ((1u << 18) - 1); }
    else { unsigned j = i - (4u << 18); r = 4 + (j >> 19); off = j & ((1u << 19) - 1); }
    float4 v = reinterpret_cast<const float4*>(p.src[r])[off];
    uint2 hp, lp; split4(&v.x, hp, lp);
    reinterpret_cast<uint2*>(p.hi[r])[off] = hp;
    reinterpret_cast<uint2*>(p.lo[r])[off] = lp;
}

// -------------- depthwise conv1d (k=3, pad=1) + bias + SiLU (vec4) ----------
__global__ void conv_silu_bf16_v4(const float* __restrict__ x,
                                  const float* __restrict__ w, const float* __restrict__ b,
                                  uint16_t* __restrict__ yh, uint16_t* __restrict__ yl)
{
    size_t i4 = (size_t)blockIdx.x * blockDim.x + threadIdx.x;
    const size_t n4 = SZ_D / 4;
    if (i4 >= n4) return;
    const size_t idx = i4 * 4;
    const int d = (int)(idx % DM);
    const int t = (int)((idx / DM) % LSEQ);

    float4 xc = *reinterpret_cast<const float4*>(x + idx);
    float4 xm = make_float4(0.f, 0.f, 0.f, 0.f);
    float4 xp = make_float4(0.f, 0.f, 0.f, 0.f);
    if (t > 0)        xm = *reinterpret_cast<const float4*>(x + idx - DM);
    if (t < LSEQ - 1) xp = *reinterpret_cast<const float4*>(x + idx + DM);
    float4 wA = *reinterpret_cast<const float4*>(w + (size_t)d * 3);
    float4 wB = *reinterpret_cast<const float4*>(w + (size_t)d * 3 + 4);
    float4 wC = *reinterpret_cast<const float4*>(w + (size_t)d * 3 + 8);
    const float wf[12] = {wA.x, wA.y, wA.z, wA.w, wB.x, wB.y, wB.z, wB.w,
                          wC.x, wC.y, wC.z, wC.w};
    float4 bb = *reinterpret_cast<const float4*>(b + d);
    const float xmv[4] = {xm.x, xm.y, xm.z, xm.w};
    const float xcv[4] = {xc.x, xc.y, xc.z, xc.w};
    const float xpv[4] = {xp.x, xp.y, xp.z, xp.w};
    const float bv[4]  = {bb.x, bb.y, bb.z, bb.w};
    float out[4];
#pragma unroll
    for (int k = 0; k < 4; ++k) {
        float s = bv[k];
        s = fmaf(wf[k * 3 + 0], xmv[k], s);
        s = fmaf(wf[k * 3 + 1], xcv[k], s);
        s = fmaf(wf[k * 3 + 2], xpv[k], s);
        out[k] = siluf(s);
    }
    uint2 hp, lp; split4(out, hp, lp);
    reinterpret_cast<uint2*>(yh)[i4] = hp;
    reinterpret_cast<uint2*>(yl)[i4] = lp;
}

// -------------- chunked scan, abar fused (vec4 across channels) -------------
__device__ __forceinline__ float abar_of(float dl, float at) {
    return __expf(-softplusf(dl) * at);
}

__global__ void scan_p1_v4(const float* __restrict__ DL, const float* __restrict__ AT,
                           const float* __restrict__ BX,
                           float* __restrict__ P, float* __restrict__ Q)
{
    unsigned i = blockIdx.x * blockDim.x + threadIdx.x;
    const unsigned tot4 = (unsigned)(BD * NCHK * DH / 4);
    if (i >= tot4) return;
    const unsigned idx = i * 4;
    const int hc = (int)(idx % DH);
    const int c  = (int)((idx / DH) % NCHK);
    const int b  = (int)(idx / (DH * NCHK));
    const size_t base = ((size_t)b * LSEQ + (size_t)c * LCHK) * DH + hc;
    float a[4] = {1.f, 1.f, 1.f, 1.f}, q[4] = {0.f, 0.f, 0.f, 0.f};
#pragma unroll 2
    for (int t = 0; t < LCHK; ++t) {
        const size_t off = base + (size_t)t * DH;
        float4 dl = *reinterpret_cast<const float4*>(DL + off);
        float4 at = *reinterpret_cast<const float4*>(AT + off);
        float4 bx = *reinterpret_cast<const float4*>(BX + off);
        const float dlv[4] = {dl.x, dl.y, dl.z, dl.w};
        const float atv[4] = {at.x, at.y, at.z, at.w};
        const float bxv[4] = {bx.x, bx.y, bx.z, bx.w};
#pragma unroll
        for (int k = 0; k < 4; ++k) {
            a[k] *= abar_of(dlv[k], atv[k]);
            q[k] = fmaf(bxv[k], a[k], q[k]);
        }
    }
    const size_t ci = ((size_t)b * NCHK + c) * DH + hc;
    *reinterpret_cast<float4*>(P + ci) = make_float4(a[0], a[1], a[2], a[3]);
    *reinterpret_cast<float4*>(Q + ci) = make_float4(q[0], q[1], q[2], q[3]);
}

__global__ void scan_p2_v4(float* __restrict__ P, float* __restrict__ Q)
{
    unsigned i = blockIdx.x * blockDim.x + threadIdx.x;
    const unsigned tot4 = (unsigned)(BD * DH / 4);
    if (i >= tot4) return;
    const unsigned idx = i * 4;
    const int b  = (int)(idx / DH);
    const int hc = (int)(idx % DH);
    float a[4] = {1.f, 1.f, 1.f, 1.f}, s[4] = {0.f, 0.f, 0.f, 0.f};
    for (int c = 0; c < NCHK; ++c) {
        const size_t ci = ((size_t)b * NCHK + c) * DH + hc;
        float4 tp = *reinterpret_cast<float4*>(P + ci);
        float4 tq = *reinterpret_cast<float4*>(Q + ci);
        *reinterpret_cast<float4*>(P + ci) = make_float4(a[0], a[1], a[2], a[3]);
        *reinterpret_cast<float4*>(Q + ci) = make_float4(s[0], s[1], s[2], s[3]);
        const float tpv[4] = {tp.x, tp.y, tp.z, tp.w};
        const float tqv[4] = {tq.x, tq.y, tq.z, tq.w};
#pragma unroll
        for (int k = 0; k < 4; ++k) {
            s[k] = fmaf(a[k], tqv[k], s[k]);
            a[k] *= tpv[k];
        }
    }
}

__global__ void scan_p3_v4(const float* __restrict__ DL, const float* __restrict__ AT,
                           const float* __restrict__ BX,
                           const float* __restrict__ Ain, const float* __restrict__ Sin,
                           uint16_t* __restrict__ hh, uint16_t* __restrict__ hl)
{
    unsigned i = blockIdx.x * blockDim.x + threadIdx.x;
    const unsigned tot4 = (unsigned)(BD * NCHK * DH / 4);
    if (i >= tot4) return;
    const unsigned idx = i * 4;
    const int hc = (int)(idx % DH);
    const int c  = (int)((idx / DH) % NCHK);
    const int b  = (int)(idx / (DH * NCHK));
    const size_t base = ((size_t)b * LSEQ + (size_t)c * LCHK) * DH + hc;
    const size_t ci = ((size_t)b * NCHK + c) * DH + hc;
    float4 a4 = *reinterpret_cast<const float4*>(Ain + ci);
    float4 s4 = *reinterpret_cast<const float4*>(Sin + ci);
    float a[4] = {a4.x, a4.y, a4.z, a4.w};
    float s[4] = {s4.x, s4.y, s4.z, s4.w};
#pragma unroll 2
    for (int t = 0; t < LCHK; ++t) {
        const size_t off = base + (size_t)t * DH;
        float4 dl = *reinterpret_cast<const float4*>(DL + off);
        float4 at = *reinterpret_cast<const float4*>(AT + off);
        float4 bx = *reinterpret_cast<const float4*>(BX + off);
        const float dlv[4] = {dl.x, dl.y, dl.z, dl.w};
        const float atv[4] = {at.x, at.y, at.z, at.w};
        const float bxv[4] = {bx.x, bx.y, bx.z, bx.w};
#pragma unroll
        for (int k = 0; k < 4; ++k) {
            a[k] *= abar_of(dlv[k], atv[k]);
            s[k] = fmaf(bxv[k], a[k], s[k]);
        }
        uint2 hp, lp; split4(s, hp, lp);
        reinterpret_cast<uint2*>(hh)[off / 4] = hp;
        reinterpret_cast<uint2*>(hl)[off / 4] = lp;
    }
}

// ---------------------------------------------------------------------------
extern "C" void kernel_launch(void* const* d_in, const int* in_sizes, int n_in,
                              void* d_out, int out_size)
{
    const float* x      = (const float*)d_in[0];
    const float* w1     = (const float*)d_in[1];
    const float* w2     = (const float*)d_in[2];
    const float* w3     = (const float*)d_in[3];
    const float* conv_w = (const float*)d_in[4];
    const float* conv_b = (const float*)d_in[5];
    const float* A_w    = (const float*)d_in[6];
    const float* A_b    = (const float*)d_in[7];
    const float* B_w    = (const float*)d_in[8];
    const float* B_b    = (const float*)d_in[9];
    const float* C_w    = (const float*)d_in[10];
    const float* C_b    = (const float*)d_in[11];
    const float* D_w    = (const float*)d_in[12];
    const float* D_b    = (const float*)d_in[13];
    const float* dl_w   = (const float*)d_in[14];
    const float* dl_b   = (const float*)d_in[15];
    float* out = (float*)d_out;

    float *x1, *h1, *h2, *h3, *ssm, *z, *Pc, *Qc;
    uint16_t *xh, *xl, *xch, *xcl, *hh, *hl, *sh, *sl, *zh, *zl;
    uint16_t *w1h, *w1l, *w2h, *w2l, *w3h, *w3l, *Dwh, *Dwl;
    uint16_t *Awh, *Awl, *Bwh, *Bwl, *dlh, *dll, *Cwh, *Cwl;
    cudaGetSymbolAddress((void**)&x1,  g_x1);
    cudaGetSymbolAddress((void**)&h1,  g_h1);
    cudaGetSymbolAddress((void**)&h2,  g_h2);
    cudaGetSymbolAddress((void**)&h3,  g_h3);
    cudaGetSymbolAddress((void**)&ssm, g_ssm);
    cudaGetSymbolAddress((void**)&z,   g_z);
    cudaGetSymbolAddress((void**)&Pc,  g_P);
    cudaGetSymbolAddress((void**)&Qc,  g_Q);
    cudaGetSymbolAddress((void**)&xh,  gxh);  cudaGetSymbolAddress((void**)&xl,  gxl);
    cudaGetSymbolAddress((void**)&xch, gxch); cudaGetSymbolAddress((void**)&xcl, gxcl);
    cudaGetSymbolAddress((void**)&hh,  ghh);  cudaGetSymbolAddress((void**)&hl,  ghl);
    cudaGetSymbolAddress((void**)&sh,  gsh);  cudaGetSymbolAddress((void**)&sl,  gsl);
    cudaGetSymbolAddress((void**)&zh,  gzh);  cudaGetSymbolAddress((void**)&zl,  gzl);
    cudaGetSymbolAddress((void**)&w1h, gw1h); cudaGetSymbolAddress((void**)&w1l, gw1l);
    cudaGetSymbolAddress((void**)&w2h, gw2h); cudaGetSymbolAddress((void**)&w2l, gw2l);
    cudaGetSymbolAddress((void**)&w3h, gw3h); cudaGetSymbolAddress((void**)&w3l, gw3l);
    cudaGetSymbolAddress((void**)&Dwh, gDwh); cudaGetSymbolAddress((void**)&Dwl, gDwl);
    cudaGetSymbolAddress((void**)&Awh, gAwh); cudaGetSymbolAddress((void**)&Awl, gAwl);
    cudaGetSymbolAddress((void**)&Bwh, gBwh); cudaGetSymbolAddress((void**)&Bwl, gBwl);
    cudaGetSymbolAddress((void**)&dlh, gdlh); cudaGetSymbolAddress((void**)&dll, gdll);
    cudaGetSymbolAddress((void**)&Cwh, gCwh); cudaGetSymbolAddress((void**)&Cwl, gCwl);

    cudaFuncSetAttribute(gemm_mma<EP_NONE, false>,    cudaFuncAttributeMaxDynamicSharedMemorySize, GEMM_SMEM);
    cudaFuncSetAttribute(gemm_mma<EP_ACCUM, true>,    cudaFuncAttributeMaxDynamicSharedMemorySize, GEMM_SMEM);
    cudaFuncSetAttribute(gemm_mma<EP_MUL_SILU, true>, cudaFuncAttributeMaxDynamicSharedMemorySize, GEMM_SMEM);
    cudaFuncSetAttribute(gemm_mma<EP_ADD_AUX, false>, cudaFuncAttributeMaxDynamicSharedMemorySize, GEMM_SMEM);

    const dim3 blk(256);
    const dim3 gD(DM / 128, MROWS / 128);   // N=1024 -> (8,128)
    const dim3 gH(DH / 128, MROWS / 128);   // N=2048 -> (16,128)

    // 0) cvt x
    {
        size_t n4 = SZ_D / 4;
        cvt_split<<<(unsigned)((n4 + 255) / 256), 256>>>(x, xh, xl, n4);
    }
    // 1) all 8 weight conversions in one launch
    {
        CvtPack p;
        p.src[0] = w1;  p.hi[0] = w1h; p.lo[0] = w1l;
        p.src[1] = w2;  p.hi[1] = w2h; p.lo[1] = w2l;
        p.src[2] = w3;  p.hi[2] = w3h; p.lo[2] = w3l;
        p.src[3] = D_w; p.hi[3] = Dwh; p.lo[3] = Dwl;
        p.src[4] = A_w; p.hi[4] = Awh; p.lo[4] = Awl;
        p.src[5] = B_w; p.hi[5] = Bwh; p.lo[5] = Bwl;
        p.src[6] = dl_w; p.hi[6] = dlh; p.lo[6] = dll;
        p.src[7] = C_w; p.hi[7] = Cwh; p.lo[7] = Cwl;
        cvt_split8<<<(CVT8_N4 + 255) / 256, 256>>>(p);
    }
    // 2) x1 = x @ w1^T
    gemm_mma<EP_NONE, false><<<gD, blk, GEMM_SMEM>>>(xh, xl, w1h, w1l, nullptr, nullptr,
                                                     x1, nullptr, nullptr, MROWS, DM, DM);
    // 3) xc = silu(conv(x1)+b) -> bf16 planes
    {
        size_t n4 = SZ_D / 4;
        conv_silu_bf16_v4<<<(unsigned)((n4 + 255) / 256), 256>>>(x1, conv_w, conv_b, xch, xcl);
    }
    // 4) dl GEMM
    gemm_mma<EP_NONE, false><<<gH, blk, GEMM_SMEM>>>(xch, xcl, dlh, dll, dl_b, nullptr,
                                                     h1, nullptr, nullptr, MROWS, DH, DM);
    // 5) A_t GEMM  <-- ncu -s 5 capture target
    gemm_mma<EP_NONE, false><<<gH, blk, GEMM_SMEM>>>(xch, xcl, Awh, Awl, A_b, nullptr,
                                                     h2, nullptr, nullptr, MROWS, DH, DM);
    // 6) B_x GEMM
    gemm_mma<EP_NONE, false><<<gH, blk, GEMM_SMEM>>>(xch, xcl, Bwh, Bwl, B_b, nullptr,
                                                     h3, nullptr, nullptr, MROWS, DH, DM);
    // 7) ssm = xc @ D_w^T + D_b
    gemm_mma<EP_NONE, false><<<gD, blk, GEMM_SMEM>>>(xch, xcl, Dwh, Dwl, D_b, nullptr,
                                                     ssm, nullptr, nullptr, MROWS, DM, DM);
    // 8-10) chunked scan with fused abar -> h bf16 planes
    {
        const unsigned tot4 = (unsigned)(BD * NCHK * DH / 4);
        scan_p1_v4<<<(tot4 + 255) / 256, 256>>>(h1, h2, h3, Pc, Qc);
        scan_p2_v4<<<((unsigned)(BD * DH / 4) + 255) / 256, 256>>>(Pc, Qc);
        scan_p3_v4<<<(tot4 + 255) / 256, 256>>>(h1, h2, h3, Pc, Qc, hh, hl);
    }
    // 11) ssm += h @ C_w^T + C_b   (emit ssm bf16 planes)
    gemm_mma<EP_ACCUM, true><<<gD, blk, GEMM_SMEM>>>(hh, hl, Cwh, Cwl, C_b, nullptr,
                                                     ssm, sh, sl, MROWS, DM, DH);
    // 12) z = ssm * silu(ssm @ w2^T)  (emit z bf16 planes)
    gemm_mma<EP_MUL_SILU, true><<<gD, blk, GEMM_SMEM>>>(sh, sl, w2h, w2l, nullptr, ssm,
                                                        z, zh, zl, MROWS, DM, DM);
    // 13) out = ssm + z @ w3^T
    gemm_mma<EP_ADD_AUX, false><<<gD, blk, GEMM_SMEM>>>(zh, zl, w3h, w3l, nullptr, ssm,
                                                        out, nullptr, nullptr, MROWS, DM, DM);
}

// round 14
// speedup vs baseline: 3.3129x; 1.0092x over previous
#include <cuda_runtime.h>
#include <cuda_bf16.h>
#include <math.h>
#include <stdint.h>

// Problem dims (fixed by the dataset)
#define BD   4
#define LSEQ 4096
#define DM   1024
#define DH   2048
#define MROWS (BD * LSEQ)   // 16384
#define NCHK 64
#define LCHK 64             // NCHK*LCHK == LSEQ

static constexpr size_t SZ_D = (size_t)MROWS * DM;   // 16.78M
static constexpr size_t SZ_H = (size_t)MROWS * DH;   // 33.55M

// ---------------- scratch (no allocations allowed) ----------------
__device__ float g_x1 [SZ_D];
__device__ float g_h1 [SZ_H];   // dl pre-activation
__device__ float g_h2 [SZ_H];   // A_bar (emitted by A_t GEMM epilogue)
__device__ float g_h3 [SZ_H];   // B_x
__device__ float g_ssm[SZ_D];
__device__ float g_z  [SZ_D];
// scan carries: [BD][NCHK][DH]
__device__ float g_P [(size_t)BD * NCHK * DH];
__device__ float g_Q [(size_t)BD * NCHK * DH];

// bf16 hi/lo planes for activations
__device__ uint16_t gxh [SZ_D], gxl [SZ_D];
__device__ uint16_t gxch[SZ_D], gxcl[SZ_D];
__device__ uint16_t ghh [SZ_H], ghl [SZ_H];
__device__ uint16_t gsh [SZ_D], gsl [SZ_D];
__device__ uint16_t gzh [SZ_D], gzl [SZ_D];
// weights hi/lo
__device__ uint16_t gw1h[DM * DM], gw1l[DM * DM];
__device__ uint16_t gw2h[DM * DM], gw2l[DM * DM];
__device__ uint16_t gw3h[DM * DM], gw3l[DM * DM];
__device__ uint16_t gDwh[DM * DM], gDwl[DM * DM];
__device__ uint16_t gAwh[DH * DM], gAwl[DH * DM];
__device__ uint16_t gBwh[DH * DM], gBwl[DH * DM];
__device__ uint16_t gdlh[DH * DM], gdll[DH * DM];
__device__ uint16_t gCwh[DM * DH], gCwl[DM * DH];

__device__ __forceinline__ float siluf(float x) { return x / (1.0f + __expf(-x)); }
__device__ __forceinline__ float softplusf(float x) {
    return (x > 15.0f) ? x : __logf(1.0f + __expf(x));
}

__device__ __forceinline__ uint32_t smem_u32(const void* p) {
    uint32_t a;
    asm("{ .reg .u64 t; cvta.to.shared.u64 t, %1; cvt.u32.u64 %0, t; }" : "=r"(a) : "l"(p));
    return a;
}

#define CP_ASYNC16(s, g) \
    asm volatile("cp.async.cg.shared.global [%0], [%1], 16;" :: "r"(s), "l"(g) : "memory")
#define CP_COMMIT() asm volatile("cp.async.commit_group;" ::: "memory")
#define CP_WAIT1()  asm volatile("cp.async.wait_group 1;" ::: "memory")
#define CP_WAIT0()  asm volatile("cp.async.wait_group 0;" ::: "memory")

__device__ __forceinline__ void ldsm4(uint32_t* r, uint32_t addr) {
    asm volatile("ldmatrix.sync.aligned.m8n8.x4.shared.b16 {%0,%1,%2,%3}, [%4];"
                 : "=r"(r[0]), "=r"(r[1]), "=r"(r[2]), "=r"(r[3]) : "r"(addr));
}

__device__ __forceinline__ void mma_bf16(float* c, const uint32_t* a, const uint32_t* b) {
    asm volatile(
        "mma.sync.aligned.m16n8k16.row.col.f32.bf16.bf16.f32 "
        "{%0,%1,%2,%3}, {%4,%5,%6,%7}, {%8,%9}, {%0,%1,%2,%3};"
        : "+f"(c[0]), "+f"(c[1]), "+f"(c[2]), "+f"(c[3])
        : "r"(a[0]), "r"(a[1]), "r"(a[2]), "r"(a[3]), "r"(b[0]), "r"(b[1]));
}

__device__ __forceinline__ uint16_t bf16h(float x) {
    return __bfloat16_as_ushort(__float2bfloat16(x));
}
__device__ __forceinline__ float bf16f(uint16_t u) {
    return __bfloat162float(__ushort_as_bfloat16(u));
}
__device__ __forceinline__ void split4(const float* v, uint2& hp, uint2& lp) {
    uint16_t h0 = bf16h(v[0]), h1 = bf16h(v[1]), h2 = bf16h(v[2]), h3 = bf16h(v[3]);
    uint16_t l0 = bf16h(v[0] - bf16f(h0));
    uint16_t l1 = bf16h(v[1] - bf16f(h1));
    uint16_t l2 = bf16h(v[2] - bf16f(h2));
    uint16_t l3 = bf16h(v[3] - bf16f(h3));
    hp.x = ((uint32_t)h1 << 16) | h0; hp.y = ((uint32_t)h3 << 16) | h2;
    lp.x = ((uint32_t)l1 << 16) | l0; lp.y = ((uint32_t)l3 << 16) | l2;
}

// SW64 swizzle for 64B rows: XOR 16B-group index (bits 5:4) with row bits (9:7)>>3
__device__ __forceinline__ uint32_t sw64(uint32_t off) { return off ^ ((off >> 3) & 0x30); }

// ===================== bf16-split GEMM on mma.sync =====================
// C[M,N] = A[M,K] @ B[N,K]^T. CTA 128x128, BK=32 bf16 (64B rows, SW64 swizzle),
// 3-stage cp.async ring, 8 warps @ 64x32, 2 CTAs/SM, 1 syncthreads per chunk.
enum { EP_NONE = 0, EP_ACCUM = 1, EP_MUL_SILU = 2, EP_ADD_AUX = 3, EP_ABAR = 4 };

static constexpr int RS    = 64;           // SMEM row stride (bytes) — no pad, swizzled
static constexpr int PLANE = 128 * RS;     // 8192
static constexpr int STG   = 4 * PLANE;    // 32768 (Ahi|Alo|Bhi|Blo)
static constexpr int NSTG  = 3;
static constexpr int GEMM_SMEM = NSTG * STG;   // 98304 -> 2 CTAs/SM

template <int EP, bool EMIT>
__global__ __launch_bounds__(256, 2) void gemm_mma(
    const uint16_t* __restrict__ Ah, const uint16_t* __restrict__ Al,
    const uint16_t* __restrict__ Bh, const uint16_t* __restrict__ Bl,
    const float* __restrict__ bias, const float* __restrict__ aux,
    float* __restrict__ C, uint16_t* __restrict__ Ch, uint16_t* __restrict__ Cl,
    int M, int N, int K)
{
    extern __shared__ char smem[];
    const uint32_t sb = smem_u32(smem);
    const int tid = threadIdx.x;
    const int wid = tid >> 5, l = tid & 31;
    const int warp_m = (wid >> 2) * 64;
    const int warp_n = (wid & 3) * 32;
    const int mtile = blockIdx.y, ntile = blockIdx.x;
    const int nch = K >> 5;

    const int ld_row = tid >> 2;
    const int ld_ch  = tid & 3;
    const size_t arow = (size_t)mtile * 128;
    const size_t brow = (size_t)ntile * 128;
    const uint32_t woff = sw64((uint32_t)(ld_row * RS + ld_ch * 16));

    auto load_stage = [&](int s, int c) {
        const uint32_t st = sb + s * STG;
        const size_t kc = (size_t)c << 5;
        const uint16_t* gp0 = Ah + (arow + ld_row) * (size_t)K + kc + ld_ch * 8;
        const uint16_t* gp1 = Al + (arow + ld_row) * (size_t)K + kc + ld_ch * 8;
        const uint16_t* gp2 = Bh + (brow + ld_row) * (size_t)K + kc + ld_ch * 8;
        const uint16_t* gp3 = Bl + (brow + ld_row) * (size_t)K + kc + ld_ch * 8;
        const uint32_t s0 = st + woff;
        const size_t stp = (size_t)64 * K;
        CP_ASYNC16(s0,                  gp0);
        CP_ASYNC16(s0 + 4096,           gp0 + stp);   // +64 rows
        CP_ASYNC16(s0 + PLANE,          gp1);
        CP_ASYNC16(s0 + PLANE + 4096,   gp1 + stp);
        CP_ASYNC16(s0 + 2*PLANE,        gp2);
        CP_ASYNC16(s0 + 2*PLANE + 4096, gp2 + stp);
        CP_ASYNC16(s0 + 3*PLANE,        gp3);
        CP_ASYNC16(s0 + 3*PLANE + 4096, gp3 + stp);
    };

    const int arow_l = warp_m + (l & 7) + ((l >> 3) & 1) * 8;
    const uint32_t aL = sb + sw64((uint32_t)(arow_l * RS + (l >> 4) * 16));
    const int brow_l = warp_n + (l & 7) + (l >> 4) * 8;
    const uint32_t bL = sb + 2 * PLANE + sw64((uint32_t)(brow_l * RS + ((l >> 3) & 1) * 16));

    float acc[4][4][4];
#pragma unroll
    for (int i = 0; i < 4; i++)
#pragma unroll
        for (int j = 0; j < 4; j++)
#pragma unroll
            for (int e = 0; e < 4; e++) acc[i][j][e] = 0.0f;

    load_stage(0, 0); CP_COMMIT();
    load_stage(1, 1); CP_COMMIT();

    int sidx = 0;   // stage of chunk c
    for (int c = 0; c < nch; ++c) {
        if (c + 1 < nch) CP_WAIT1(); else CP_WAIT0();
        __syncthreads();            // stage c visible CTA-wide; stage (c-1) reads done
        if (c + 2 < nch) {
            int s2 = sidx + 2; if (s2 >= NSTG) s2 -= NSTG;
            load_stage(s2, c + 2);  // overwrites buffer of chunk c-1
            CP_COMMIT();
        }

        const uint32_t so = (uint32_t)(sidx * STG);
#pragma unroll
        for (int ks = 0; ks < 2; ++ks) {
            const uint32_t ao = (aL + so) ^ (ks << 5);
            const uint32_t bo = (bL + so) ^ (ks << 5);
            uint32_t afh[4][4], afl[4][4], bfh[4][2], bfl[4][2];
#pragma unroll
            for (int mt = 0; mt < 4; ++mt) {
                ldsm4(afh[mt], ao + mt * 16 * RS);
                ldsm4(afl[mt], ao + PLANE + mt * 16 * RS);
            }
#pragma unroll
            for (int j = 0; j < 2; ++j) {
                uint32_t t[4];
                ldsm4(t, bo + j * 16 * RS);
                bfh[2*j][0] = t[0]; bfh[2*j][1] = t[1];
                bfh[2*j+1][0] = t[2]; bfh[2*j+1][1] = t[3];
                ldsm4(t, bo + PLANE + j * 16 * RS);
                bfl[2*j][0] = t[0]; bfl[2*j][1] = t[1];
                bfl[2*j+1][0] = t[2]; bfl[2*j+1][1] = t[3];
            }
#pragma unroll
            for (int mt = 0; mt < 4; ++mt)
#pragma unroll
                for (int nt = 0; nt < 4; ++nt) {
                    mma_bf16(acc[mt][nt], afh[mt], bfh[nt]);
                    mma_bf16(acc[mt][nt], afh[mt], bfl[nt]);
                    mma_bf16(acc[mt][nt], afl[mt], bfh[nt]);
                }
        }
        if (++sidx == NSTG) sidx = 0;
    }

    // epilogue
    const int mrow0 = mtile * 128 + warp_m + (l >> 2);
    const int coln0 = ntile * 128 + warp_n + (l & 3) * 2;
#pragma unroll
    for (int mt = 0; mt < 4; ++mt) {
#pragma unroll
        for (int nt = 0; nt < 4; ++nt) {
            const int col = coln0 + nt * 8;
#pragma unroll
            for (int h = 0; h < 2; ++h) {
                const int row = mrow0 + mt * 16 + h * 8;
                float v0 = acc[mt][nt][h * 2 + 0];
                float v1 = acc[mt][nt][h * 2 + 1];
                if (bias) { v0 += bias[col]; v1 += bias[col + 1]; }
                const size_t idx = (size_t)row * N + col;
                if (EP == EP_ACCUM) {
                    float2 cv = *reinterpret_cast<const float2*>(&C[idx]);
                    v0 += cv.x; v1 += cv.y;
                } else if (EP == EP_MUL_SILU) {
                    float2 av = *reinterpret_cast<const float2*>(&aux[idx]);
                    v0 = av.x * siluf(v0); v1 = av.y * siluf(v1);
                } else if (EP == EP_ADD_AUX) {
                    float2 av = *reinterpret_cast<const float2*>(&aux[idx]);
                    v0 = av.x + v0; v1 = av.y + v1;
                } else if (EP == EP_ABAR) {
                    // aux = dl pre-activation; acc+bias = A_t; emit exp(-softplus(dl)*A_t)
                    float2 av = *reinterpret_cast<const float2*>(&aux[idx]);
                    v0 = __expf(-softplusf(av.x) * v0);
                    v1 = __expf(-softplusf(av.y) * v1);
                }
                float2 ov; ov.x = v0; ov.y = v1;
                *reinterpret_cast<float2*>(&C[idx]) = ov;
                if (EMIT) {
                    uint16_t h0 = bf16h(v0), h1 = bf16h(v1);
                    uint16_t l0 = bf16h(v0 - bf16f(h0)), l1 = bf16h(v1 - bf16f(h1));
                    *reinterpret_cast<uint32_t*>(&Ch[idx]) = ((uint32_t)h1 << 16) | h0;
                    *reinterpret_cast<uint32_t*>(&Cl[idx]) = ((uint32_t)l1 << 16) | l0;
                }
            }
        }
    }
}

// -------------- fp32 -> bf16 hi/lo split (x input) --------------------------
__global__ void cvt_split(const float* __restrict__ x, uint16_t* __restrict__ hi,
                          uint16_t* __restrict__ lo, size_t n4)
{
    size_t i = (size_t)blockIdx.x * blockDim.x + threadIdx.x;
    if (i >= n4) return;
    float4 v = reinterpret_cast<const float4*>(x)[i];
    uint2 hp, lp; split4(&v.x, hp, lp);
    reinterpret_cast<uint2*>(hi)[i] = hp;
    reinterpret_cast<uint2*>(lo)[i] = lp;
}

// -------------- batched weight conversions (8 tensors, one launch) ----------
struct CvtPack {
    const float* src[8];
    uint16_t* hi[8];
    uint16_t* lo[8];
};
static constexpr unsigned CVT8_N4 = (4u << 18) + (4u << 19);   // 3145728

__global__ void cvt_split8(CvtPack p)
{
    unsigned i = blockIdx.x * blockDim.x + threadIdx.x;
    if (i >= CVT8_N4) return;
    unsigned r, off;
    if (i < (4u << 18)) { r = i >> 18;              off = i & ((1u << 18) - 1); }
    else { unsigned j = i - (4u << 18); r = 4 + (j >> 19); off = j & ((1u << 19) - 1); }
    float4 v = reinterpret_cast<const float4*>(p.src[r])[off];
    uint2 hp, lp; split4(&v.x, hp, lp);
    reinterpret_cast<uint2*>(p.hi[r])[off] = hp;
    reinterpret_cast<uint2*>(p.lo[r])[off] = lp;
}

// -------------- depthwise conv1d (k=3, pad=1) + bias + SiLU (vec4) ----------
__global__ void conv_silu_bf16_v4(const float* __restrict__ x,
                                  const float* __restrict__ w, const float* __restrict__ b,
                                  uint16_t* __restrict__ yh, uint16_t* __restrict__ yl)
{
    size_t i4 = (size_t)blockIdx.x * blockDim.x + threadIdx.x;
    const size_t n4 = SZ_D / 4;
    if (i4 >= n4) return;
    const size_t idx = i4 * 4;
    const int d = (int)(idx % DM);
    const int t = (int)((idx / DM) % LSEQ);

    float4 xc = *reinterpret_cast<const float4*>(x + idx);
    float4 xm = make_float4(0.f, 0.f, 0.f, 0.f);
    float4 xp = make_float4(0.f, 0.f, 0.f, 0.f);
    if (t > 0)        xm = *reinterpret_cast<const float4*>(x + idx - DM);
    if (t < LSEQ - 1) xp = *reinterpret_cast<const float4*>(x + idx + DM);
    float4 wA = *reinterpret_cast<const float4*>(w + (size_t)d * 3);
    float4 wB = *reinterpret_cast<const float4*>(w + (size_t)d * 3 + 4);
    float4 wC = *reinterpret_cast<const float4*>(w + (size_t)d * 3 + 8);
    const float wf[12] = {wA.x, wA.y, wA.z, wA.w, wB.x, wB.y, wB.z, wB.w,
                          wC.x, wC.y, wC.z, wC.w};
    float4 bb = *reinterpret_cast<const float4*>(b + d);
    const float xmv[4] = {xm.x, xm.y, xm.z, xm.w};
    const float xcv[4] = {xc.x, xc.y, xc.z, xc.w};
    const float xpv[4] = {xp.x, xp.y, xp.z, xp.w};
    const float bv[4]  = {bb.x, bb.y, bb.z, bb.w};
    float out[4];
#pragma unroll
    for (int k = 0; k < 4; ++k) {
        float s = bv[k];
        s = fmaf(wf[k * 3 + 0], xmv[k], s);
        s = fmaf(wf[k * 3 + 1], xcv[k], s);
        s = fmaf(wf[k * 3 + 2], xpv[k], s);
        out[k] = siluf(s);
    }
    uint2 hp, lp; split4(out, hp, lp);
    reinterpret_cast<uint2*>(yh)[i4] = hp;
    reinterpret_cast<uint2*>(yl)[i4] = lp;
}

// -------------- chunked scan over precomputed A_bar (vec4) ------------------
__global__ void scan_p1_v4(const float* __restrict__ AB, const float* __restrict__ BX,
                           float* __restrict__ P, float* __restrict__ Q)
{
    unsigned i = blockIdx.x * blockDim.x + threadIdx.x;
    const unsigned tot4 = (unsigned)(BD * NCHK * DH / 4);
    if (i >= tot4) return;
    const unsigned idx = i * 4;
    const int hc = (int)(idx % DH);
    const int c  = (int)((idx / DH) % NCHK);
    const int b  = (int)(idx / (DH * NCHK));
    const size_t base = ((size_t)b * LSEQ + (size_t)c * LCHK) * DH + hc;
    float a[4] = {1.f, 1.f, 1.f, 1.f}, q[4] = {0.f, 0.f, 0.f, 0.f};
#pragma unroll 4
    for (int t = 0; t < LCHK; ++t) {
        const size_t off = base + (size_t)t * DH;
        float4 ab = *reinterpret_cast<const float4*>(AB + off);
        float4 bx = *reinterpret_cast<const float4*>(BX + off);
        const float abv[4] = {ab.x, ab.y, ab.z, ab.w};
        const float bxv[4] = {bx.x, bx.y, bx.z, bx.w};
#pragma unroll
        for (int k = 0; k < 4; ++k) {
            a[k] *= abv[k];
            q[k] = fmaf(bxv[k], a[k], q[k]);
        }
    }
    const size_t ci = ((size_t)b * NCHK + c) * DH + hc;
    *reinterpret_cast<float4*>(P + ci) = make_float4(a[0], a[1], a[2], a[3]);
    *reinterpret_cast<float4*>(Q + ci) = make_float4(q[0], q[1], q[2], q[3]);
}

__global__ void scan_p2_v4(float* __restrict__ P, float* __restrict__ Q)
{
    unsigned i = blockIdx.x * blockDim.x + threadIdx.x;
    const unsigned tot4 = (unsigned)(BD * DH / 4);
    if (i >= tot4) return;
    const unsigned idx = i * 4;
    const int b  = (int)(idx / DH);
    const int hc = (int)(idx % DH);
    float a[4] = {1.f, 1.f, 1.f, 1.f}, s[4] = {0.f, 0.f, 0.f, 0.f};
    for (int c = 0; c < NCHK; ++c) {
        const size_t ci = ((size_t)b * NCHK + c) * DH + hc;
        float4 tp = *reinterpret_cast<float4*>(P + ci);
        float4 tq = *reinterpret_cast<float4*>(Q + ci);
        *reinterpret_cast<float4*>(P + ci) = make_float4(a[0], a[1], a[2], a[3]);
        *reinterpret_cast<float4*>(Q + ci) = make_float4(s[0], s[1], s[2], s[3]);
        const float tpv[4] = {tp.x, tp.y, tp.z, tp.w};
        const float tqv[4] = {tq.x, tq.y, tq.z, tq.w};
#pragma unroll
        for (int k = 0; k < 4; ++k) {
            s[k] = fmaf(a[k], tqv[k], s[k]);
            a[k] *= tpv[k];
        }
    }
}

__global__ void scan_p3_v4(const float* __restrict__ AB, const float* __restrict__ BX,
                           const float* __restrict__ Ain, const float* __restrict__ Sin,
                           uint16_t* __restrict__ hh, uint16_t* __restrict__ hl)
{
    unsigned i = blockIdx.x * blockDim.x + threadIdx.x;
    const unsigned tot4 = (unsigned)(BD * NCHK * DH / 4);
    if (i >= tot4) return;
    const unsigned idx = i * 4;
    const int hc = (int)(idx % DH);
    const int c  = (int)((idx / DH) % NCHK);
    const int b  = (int)(idx / (DH * NCHK));
    const size_t base = ((size_t)b * LSEQ + (size_t)c * LCHK) * DH + hc;
    const size_t ci = ((size_t)b * NCHK + c) * DH + hc;
    float4 a4 = *reinterpret_cast<const float4*>(Ain + ci);
    float4 s4 = *reinterpret_cast<const float4*>(Sin + ci);
    float a[4] = {a4.x, a4.y, a4.z, a4.w};
    float s[4] = {s4.x, s4.y, s4.z, s4.w};
#pragma unroll 4
    for (int t = 0; t < LCHK; ++t) {
        const size_t off = base + (size_t)t * DH;
        float4 ab = *reinterpret_cast<const float4*>(AB + off);
        float4 bx = *reinterpret_cast<const float4*>(BX + off);
        const float abv[4] = {ab.x, ab.y, ab.z, ab.w};
        const float bxv[4] = {bx.x, bx.y, bx.z, bx.w};
#pragma unroll
        for (int k = 0; k < 4; ++k) {
            a[k] *= abv[k];
            s[k] = fmaf(bxv[k], a[k], s[k]);
        }
        uint2 hp, lp; split4(s, hp, lp);
        reinterpret_cast<uint2*>(hh)[off / 4] = hp;
        reinterpret_cast<uint2*>(hl)[off / 4] = lp;
    }
}

// ---------------------------------------------------------------------------
extern "C" void kernel_launch(void* const* d_in, const int* in_sizes, int n_in,
                              void* d_out, int out_size)
{
    const float* x      = (const float*)d_in[0];
    const float* w1     = (const float*)d_in[1];
    const float* w2     = (const float*)d_in[2];
    const float* w3     = (const float*)d_in[3];
    const float* conv_w = (const float*)d_in[4];
    const float* conv_b = (const float*)d_in[5];
    const float* A_w    = (const float*)d_in[6];
    const float* A_b    = (const float*)d_in[7];
    const float* B_w    = (const float*)d_in[8];
    const float* B_b    = (const float*)d_in[9];
    const float* C_w    = (const float*)d_in[10];
    const float* C_b    = (const float*)d_in[11];
    const float* D_w    = (const float*)d_in[12];
    const float* D_b    = (const float*)d_in[13];
    const float* dl_w   = (const float*)d_in[14];
    const float* dl_b   = (const float*)d_in[15];
    float* out = (float*)d_out;

    float *x1, *h1, *h2, *h3, *ssm, *z, *Pc, *Qc;
    uint16_t *xh, *xl, *xch, *xcl, *hh, *hl, *sh, *sl, *zh, *zl;
    uint16_t *w1h, *w1l, *w2h, *w2l, *w3h, *w3l, *Dwh, *Dwl;
    uint16_t *Awh, *Awl, *Bwh, *Bwl, *dlh, *dll, *Cwh, *Cwl;
    cudaGetSymbolAddress((void**)&x1,  g_x1);
    cudaGetSymbolAddress((void**)&h1,  g_h1);
    cudaGetSymbolAddress((void**)&h2,  g_h2);
    cudaGetSymbolAddress((void**)&h3,  g_h3);
    cudaGetSymbolAddress((void**)&ssm, g_ssm);
    cudaGetSymbolAddress((void**)&z,   g_z);
    cudaGetSymbolAddress((void**)&Pc,  g_P);
    cudaGetSymbolAddress((void**)&Qc,  g_Q);
    cudaGetSymbolAddress((void**)&xh,  gxh);  cudaGetSymbolAddress((void**)&xl,  gxl);
    cudaGetSymbolAddress((void**)&xch, gxch); cudaGetSymbolAddress((void**)&xcl, gxcl);
    cudaGetSymbolAddress((void**)&hh,  ghh);  cudaGetSymbolAddress((void**)&hl,  ghl);
    cudaGetSymbolAddress((void**)&sh,  gsh);  cudaGetSymbolAddress((void**)&sl,  gsl);
    cudaGetSymbolAddress((void**)&zh,  gzh);  cudaGetSymbolAddress((void**)&zl,  gzl);
    cudaGetSymbolAddress((void**)&w1h, gw1h); cudaGetSymbolAddress((void**)&w1l, gw1l);
    cudaGetSymbolAddress((void**)&w2h, gw2h); cudaGetSymbolAddress((void**)&w2l, gw2l);
    cudaGetSymbolAddress((void**)&w3h, gw3h); cudaGetSymbolAddress((void**)&w3l, gw3l);
    cudaGetSymbolAddress((void**)&Dwh, gDwh); cudaGetSymbolAddress((void**)&Dwl, gDwl);
    cudaGetSymbolAddress((void**)&Awh, gAwh); cudaGetSymbolAddress((void**)&Awl, gAwl);
    cudaGetSymbolAddress((void**)&Bwh, gBwh); cudaGetSymbolAddress((void**)&Bwl, gBwl);
    cudaGetSymbolAddress((void**)&dlh, gdlh); cudaGetSymbolAddress((void**)&dll, gdll);
    cudaGetSymbolAddress((void**)&Cwh, gCwh); cudaGetSymbolAddress((void**)&Cwl, gCwl);

    cudaFuncSetAttribute(gemm_mma<EP_NONE, false>,    cudaFuncAttributeMaxDynamicSharedMemorySize, GEMM_SMEM);
    cudaFuncSetAttribute(gemm_mma<EP_ABAR, false>,    cudaFuncAttributeMaxDynamicSharedMemorySize, GEMM_SMEM);
    cudaFuncSetAttribute(gemm_mma<EP_ACCUM, true>,    cudaFuncAttributeMaxDynamicSharedMemorySize, GEMM_SMEM);
    cudaFuncSetAttribute(gemm_mma<EP_MUL_SILU, true>, cudaFuncAttributeMaxDynamicSharedMemorySize, GEMM_SMEM);
    cudaFuncSetAttribute(gemm_mma<EP_ADD_AUX, false>, cudaFuncAttributeMaxDynamicSharedMemorySize, GEMM_SMEM);

    const dim3 blk(256);
    const dim3 gD(DM / 128, MROWS / 128);   // N=1024 -> (8,128)
    const dim3 gH(DH / 128, MROWS / 128);   // N=2048 -> (16,128)

    // 0) cvt x
    {
        size_t n4 = SZ_D / 4;
        cvt_split<<<(unsigned)((n4 + 255) / 256), 256>>>(x, xh, xl, n4);
    }
    // 1) all 8 weight conversions in one launch
    {
        CvtPack p;
        p.src[0] = w1;  p.hi[0] = w1h; p.lo[0] = w1l;
        p.src[1] = w2;  p.hi[1] = w2h; p.lo[1] = w2l;
        p.src[2] = w3;  p.hi[2] = w3h; p.lo[2] = w3l;
        p.src[3] = D_w; p.hi[3] = Dwh; p.lo[3] = Dwl;
        p.src[4] = A_w; p.hi[4] = Awh; p.lo[4] = Awl;
        p.src[5] = B_w; p.hi[5] = Bwh; p.lo[5] = Bwl;
        p.src[6] = dl_w; p.hi[6] = dlh; p.lo[6] = dll;
        p.src[7] = C_w; p.hi[7] = Cwh; p.lo[7] = Cwl;
        cvt_split8<<<(CVT8_N4 + 255) / 256, 256>>>(p);
    }
    // 2) x1 = x @ w1^T
    gemm_mma<EP_NONE, false><<<gD, blk, GEMM_SMEM>>>(xh, xl, w1h, w1l, nullptr, nullptr,
                                                     x1, nullptr, nullptr, MROWS, DM, DM);
    // 3) xc = silu(conv(x1)+b) -> bf16 planes
    {
        size_t n4 = SZ_D / 4;
        conv_silu_bf16_v4<<<(unsigned)((n4 + 255) / 256), 256>>>(x1, conv_w, conv_b, xch, xcl);
    }
    // 4) dl GEMM -> h1 (pre-activation)
    gemm_mma<EP_NONE, false><<<gH, blk, GEMM_SMEM>>>(xch, xcl, dlh, dll, dl_b, nullptr,
                                                     h1, nullptr, nullptr, MROWS, DH, DM);
    // 5) A_t GEMM with fused A_bar epilogue -> h2 = exp(-softplus(h1)*(acc+A_b))
    gemm_mma<EP_ABAR, false><<<gH, blk, GEMM_SMEM>>>(xch, xcl, Awh, Awl, A_b, h1,
                                                     h2, nullptr, nullptr, MROWS, DH, DM);
    // 6) B_x GEMM -> h3
    gemm_mma<EP_NONE, false><<<gH, blk, GEMM_SMEM>>>(xch, xcl, Bwh, Bwl, B_b, nullptr,
                                                     h3, nullptr, nullptr, MROWS, DH, DM);
    // 7) ssm = xc @ D_w^T + D_b
    gemm_mma<EP_NONE, false><<<gD, blk, GEMM_SMEM>>>(xch, xcl, Dwh, Dwl, D_b, nullptr,
                                                     ssm, nullptr, nullptr, MROWS, DM, DM);
    // 8-10) chunked scan over (h2 = A_bar, h3 = B_x) -> h bf16 planes
    {
        const unsigned tot4 = (unsigned)(BD * NCHK * DH / 4);
        scan_p1_v4<<<(tot4 + 255) / 256, 256>>>(h2, h3, Pc, Qc);
        scan_p2_v4<<<((unsigned)(BD * DH / 4) + 255) / 256, 256>>>(Pc, Qc);
        scan_p3_v4<<<(tot4 + 255) / 256, 256>>>(h2, h3, Pc, Qc, hh, hl);
    }
    // 11) ssm += h @ C_w^T + C_b   (emit ssm bf16 planes)
    gemm_mma<EP_ACCUM, true><<<gD, blk, GEMM_SMEM>>>(hh, hl, Cwh, Cwl, C_b, nullptr,
                                                     ssm, sh, sl, MROWS, DM, DH);
    // 12) z = ssm * silu(ssm @ w2^T)  (emit z bf16 planes)
    gemm_mma<EP_MUL_SILU, true><<<gD, blk, GEMM_SMEM>>>(sh, sl, w2h, w2l, nullptr, ssm,
                                                        z, zh, zl, MROWS, DM, DM);
    // 13) out = ssm + z @ w3^T
    gemm_mma<EP_ADD_AUX, false><<<gD, blk, GEMM_SMEM>>>(zh, zl, w3h, w3l, nullptr, ssm,
                                                        out, nullptr, nullptr, MROWS, DM, DM);
}